// round 5
// baseline (speedup 1.0000x reference)
#include <cuda_runtime.h>
#include <cuda_bf16.h>
#include <math.h>
#include <stdint.h>

// ---------------------------------------------------------------------------
// Gemma3 prefill forward — Round 5: tensor-core GEMMs (mma.sync bf16 hi/lo
// split, fp32-grade accuracy) + split-K dense partials.
// (Round-4 design resubmitted verbatim after broker infra failure.)
// ---------------------------------------------------------------------------

#define LAY    12
#define DMODEL 1152
#define NHEAD  4
#define HDIM   256
#define FFDIM  6912
#define VOCAB  32768
#define TTOK   128
#define CCTX   1920
#define STOT   2048
#define QKVW   1536   // (NH+2)*HD

// ---- scratch (single device global, no allocations) ----
#define OFF_H     0
#define OFF_X     (OFF_H + TTOK*DMODEL)
#define OFF_QKV   (OFF_X + TTOK*DMODEL)
#define OFF_Q     (OFF_QKV + TTOK*QKVW)
#define OFF_K     (OFF_Q + NHEAD*TTOK*HDIM)
#define OFF_V     (OFF_K + STOT*HDIM)
#define OFF_SC    (OFF_V + HDIM*STOT)
#define OFF_ATT   (OFF_SC + NHEAD*TTOK*STOT)
#define OFF_PROJ  (OFF_ATT + TTOK*NHEAD*HDIM)
#define OFF_FF1   (OFF_PROJ + TTOK*DMODEL)
#define OFF_FF2   (OFF_FF1 + TTOK*FFDIM)
#define OFF_PART  (OFF_FF2 + TTOK*FFDIM)
#define PART_MAX  (2*TTOK*FFDIM)
#define SCRATCH_TOTAL (OFF_PART + PART_MAX)

__device__ float g_scratch[SCRATCH_TOTAL];

// ---------------------------------------------------------------------------
// mma.sync m16n8k16 bf16 helper
// ---------------------------------------------------------------------------
__device__ __forceinline__ void mma16816(float* c, const uint32_t* a,
                                         uint32_t b0, uint32_t b1) {
    asm volatile(
        "mma.sync.aligned.m16n8k16.row.col.f32.bf16.bf16.f32 "
        "{%0,%1,%2,%3}, {%4,%5,%6,%7}, {%8,%9}, {%0,%1,%2,%3};"
        : "+f"(c[0]), "+f"(c[1]), "+f"(c[2]), "+f"(c[3])
        : "r"(a[0]), "r"(a[1]), "r"(a[2]), "r"(a[3]), "r"(b0), "r"(b1));
}

__device__ __forceinline__ void cvt_hl(float x, __nv_bfloat16& hi, __nv_bfloat16& lo) {
    hi = __float2bfloat16(x);
    lo = __float2bfloat16(x - __bfloat162float(hi));
}

// ---------------------------------------------------------------------------
// GEMM: C[128, N] = A[128,K] @ B   (BT=0: B is KxN row-major;
//                                   BT=1: B is NxK row-major, A@B^T)
// CTA tile 128x128, 256 threads (8 warps; warp tile 32x64).
// fp32 inputs split to bf16 hi/lo in smem; 3 mma combos -> fp32-grade.
// grid = (N/128, split, batch). split>1 -> dense partials [batch][z][128][Nt].
// ---------------------------------------------------------------------------
template<bool BT>
__global__ __launch_bounds__(256) void gemm_mma(
    const float* __restrict__ A, const float* __restrict__ B, float* __restrict__ C,
    int K, int lda, int ldb, int ldc, int ktiles_split,
    long sA, long sB, long sC)
{
    __shared__ __nv_bfloat16 As[2][128 * 16];   // [hi/lo][m][k]
    __shared__ __nv_bfloat16 Bs[2][128 * 16];   // [hi/lo][n][k]

    const int tid = threadIdx.x;
    const int bz = blockIdx.z, z = blockIdx.y;
    const int bn = blockIdx.x * 128;

    const float* Ab = A + (long)bz * sA;
    const float* Bb = B + (long)bz * sB;

    const int ktot = K >> 4;
    const int kb   = z * ktiles_split;
    const int nkt  = min(ktiles_split, ktot - kb);

    // global-load indexing
    const int arow = tid >> 1, akc = (tid & 1) * 8;          // A & BT-B path
    const int bkr  = tid >> 4, bnc = (tid & 15) * 8;         // NN-B path

    float4 pa0, pa1, pb0, pb1;
    {
        const float* ap = Ab + (long)arow * lda + kb * 16 + akc;
        pa0 = *(const float4*)ap; pa1 = *(const float4*)(ap + 4);
        if (BT) {
            const float* bp = Bb + (long)(bn + arow) * ldb + kb * 16 + akc;
            pb0 = *(const float4*)bp; pb1 = *(const float4*)(bp + 4);
        } else {
            const float* bp = Bb + (long)(kb * 16 + bkr) * ldb + bn + bnc;
            pb0 = *(const float4*)bp; pb1 = *(const float4*)(bp + 4);
        }
    }

    float acc[2][8][4];
#pragma unroll
    for (int i = 0; i < 2; i++)
#pragma unroll
        for (int j = 0; j < 8; j++)
#pragma unroll
            for (int l = 0; l < 4; l++) acc[i][j][l] = 0.f;

    const int w = tid >> 5, lane = tid & 31;
    const int wm = (w & 3) * 32, wn = (w >> 2) * 64;
    const int r = lane >> 2, cp = (lane & 3) * 2;

    for (int kt = 0; kt < nkt; kt++) {
        // ---- commit prefetched tile (convert fp32 -> bf16 hi/lo) ----
        {
            const float* fa = (const float*)&pa0;
#pragma unroll
            for (int j = 0; j < 8; j++) {
                __nv_bfloat16 hi, lo;
                cvt_hl(j < 4 ? fa[j] : ((const float*)&pa1)[j - 4], hi, lo);
                As[0][arow * 16 + akc + j] = hi;
                As[1][arow * 16 + akc + j] = lo;
            }
            if (BT) {
#pragma unroll
                for (int j = 0; j < 8; j++) {
                    __nv_bfloat16 hi, lo;
                    cvt_hl(j < 4 ? ((const float*)&pb0)[j] : ((const float*)&pb1)[j - 4], hi, lo);
                    Bs[0][arow * 16 + akc + j] = hi;
                    Bs[1][arow * 16 + akc + j] = lo;
                }
            } else {
#pragma unroll
                for (int j = 0; j < 8; j++) {
                    __nv_bfloat16 hi, lo;
                    cvt_hl(j < 4 ? ((const float*)&pb0)[j] : ((const float*)&pb1)[j - 4], hi, lo);
                    Bs[0][(bnc + j) * 16 + bkr] = hi;   // transpose to [n][k]
                    Bs[1][(bnc + j) * 16 + bkr] = lo;
                }
            }
        }
        __syncthreads();

        // ---- prefetch next tile ----
        if (kt + 1 < nkt) {
            const float* ap = Ab + (long)arow * lda + (kb + kt + 1) * 16 + akc;
            pa0 = *(const float4*)ap; pa1 = *(const float4*)(ap + 4);
            if (BT) {
                const float* bp = Bb + (long)(bn + arow) * ldb + (kb + kt + 1) * 16 + akc;
                pb0 = *(const float4*)bp; pb1 = *(const float4*)(bp + 4);
            } else {
                const float* bp = Bb + (long)((kb + kt + 1) * 16 + bkr) * ldb + bn + bnc;
                pb0 = *(const float4*)bp; pb1 = *(const float4*)(bp + 4);
            }
        }

        // ---- mma over this k16 tile ----
        uint32_t afr[2][2][4];    // [hi/lo][mf][reg]
#pragma unroll
        for (int h = 0; h < 2; h++)
#pragma unroll
            for (int mf = 0; mf < 2; mf++) {
                int row = wm + mf * 16 + r;
                afr[h][mf][0] = *(const uint32_t*)&As[h][row * 16 + cp];
                afr[h][mf][1] = *(const uint32_t*)&As[h][(row + 8) * 16 + cp];
                afr[h][mf][2] = *(const uint32_t*)&As[h][row * 16 + cp + 8];
                afr[h][mf][3] = *(const uint32_t*)&As[h][(row + 8) * 16 + cp + 8];
            }
#pragma unroll
        for (int nf = 0; nf < 8; nf++) {
            int bc = (wn + nf * 8 + r) * 16 + cp;
            uint32_t bh0 = *(const uint32_t*)&Bs[0][bc];
            uint32_t bh1 = *(const uint32_t*)&Bs[0][bc + 8];
            uint32_t bl0 = *(const uint32_t*)&Bs[1][bc];
            uint32_t bl1 = *(const uint32_t*)&Bs[1][bc + 8];
#pragma unroll
            for (int mf = 0; mf < 2; mf++) {
                mma16816(acc[mf][nf], afr[0][mf], bh0, bh1);   // hi*hi
                mma16816(acc[mf][nf], afr[1][mf], bh0, bh1);   // lo*hi
                mma16816(acc[mf][nf], afr[0][mf], bl0, bl1);   // hi*lo
            }
        }
        __syncthreads();
    }

    // ---- writeback ----
    const int Nt = gridDim.x * 128;
    const bool direct = (gridDim.y == 1);
#pragma unroll
    for (int mf = 0; mf < 2; mf++)
#pragma unroll
        for (int nf = 0; nf < 8; nf++) {
            int row = wm + mf * 16 + r;
            int col = bn + wn + nf * 8 + cp;
            float* c = acc[mf][nf];
            if (direct) {
                float* p = C + (long)bz * sC + (long)row * ldc + col;
                *(float2*)p = make_float2(c[0], c[1]);
                *(float2*)(p + 8LL * ldc) = make_float2(c[2], c[3]);
            } else {
                float* p = C + ((long)(bz * gridDim.y + z) * 128 + row) * Nt + col;
                *(float2*)p = make_float2(c[0], c[1]);
                *(float2*)(p + 8LL * Nt) = make_float2(c[2], c[3]);
            }
        }
}

// Sum split-K partials: C[m*ldc + bz*Npart + n] = sum_s P[bz][s][m][n]
__global__ __launch_bounds__(256) void reduce_split(
    const float* __restrict__ P, float* __restrict__ C,
    int split, int Npart, int ldc)
{
    int bz = blockIdx.y;
    long idx = ((long)blockIdx.x * 256 + threadIdx.x) * 4;
    int m = (int)(idx / Npart);
    int n = (int)(idx % Npart);
    const float* base = P + (long)bz * split * TTOK * Npart + (long)m * Npart + n;
    float4 s = *(const float4*)base;
    for (int t = 1; t < split; t++) {
        float4 v = *(const float4*)(base + (long)t * TTOK * Npart);
        s.x += v.x; s.y += v.y; s.z += v.z; s.w += v.w;
    }
    *(float4*)(C + (long)m * ldc + bz * Npart + n) = s;
}

__device__ __forceinline__ float gelu_t(float x) {
    float x3 = x * x * x;
    return 0.5f * x * (1.f + tanhf(0.7978845608028654f * (x + 0.044715f * x3)));
}

// Reduce "up" partials, then out = gelu(gate) * up
__global__ __launch_bounds__(256) void reduce_split_gelu(
    const float* __restrict__ P, const float* __restrict__ G,
    float* __restrict__ C, int split, int Npart)
{
    long idx = ((long)blockIdx.x * 256 + threadIdx.x) * 4;
    const float* base = P + idx;
    float4 s = *(const float4*)base;
    for (int t = 1; t < split; t++) {
        float4 v = *(const float4*)(base + (long)t * TTOK * Npart);
        s.x += v.x; s.y += v.y; s.z += v.z; s.w += v.w;
    }
    float4 g = *(const float4*)(G + idx);
    s.x *= gelu_t(g.x); s.y *= gelu_t(g.y);
    s.z *= gelu_t(g.z); s.w *= gelu_t(g.w);
    *(float4*)(C + idx) = s;
}

// ---------------------------------------------------------------------------
// RMSNorm kernels
// ---------------------------------------------------------------------------
__global__ __launch_bounds__(256) void rms_kernel(
    const float* __restrict__ x, const float* __restrict__ w,
    float* __restrict__ y, int ncols)
{
    int row = blockIdx.x;
    const float* xr = x + (long)row * ncols;
    __shared__ float red[256];
    int tid = threadIdx.x;
    float ss = 0.f;
    for (int c = tid; c < ncols; c += 256) { float v = xr[c]; ss += v * v; }
    red[tid] = ss; __syncthreads();
    for (int s = 128; s > 0; s >>= 1) { if (tid < s) red[tid] += red[tid + s]; __syncthreads(); }
    float inv = rsqrtf(red[0] / ncols + 1e-6f);
    for (int c = tid; c < ncols; c += 256)
        y[(long)row * ncols + c] = xr[c] * inv * (1.f + w[c]);
}

__global__ __launch_bounds__(256) void add_rms_kernel(
    float* __restrict__ h, const float* __restrict__ p,
    const float* __restrict__ w, int ncols)
{
    int row = blockIdx.x;
    const float* pr = p + (long)row * ncols;
    __shared__ float red[256];
    int tid = threadIdx.x;
    float ss = 0.f;
    for (int c = tid; c < ncols; c += 256) { float v = pr[c]; ss += v * v; }
    red[tid] = ss; __syncthreads();
    for (int s = 128; s > 0; s >>= 1) { if (tid < s) red[tid] += red[tid + s]; __syncthreads(); }
    float inv = rsqrtf(red[0] / ncols + 1e-6f);
    for (int c = tid; c < ncols; c += 256)
        h[(long)row * ncols + c] += pr[c] * inv * (1.f + w[c]);
}

// ---------------------------------------------------------------------------
// Q/K rmsnorm + RoPE + V scatter
// ---------------------------------------------------------------------------
__global__ __launch_bounds__(256) void qk_rope_kernel(
    const float* __restrict__ qkv,
    const float* __restrict__ qw, const float* __restrict__ kw,
    const float* __restrict__ cosp, const float* __restrict__ sinp,
    float* __restrict__ qout, float* __restrict__ Kfull, float* __restrict__ Vfull,
    float* __restrict__ kslice, float* __restrict__ vslice)
{
    int t = blockIdx.x;
    int d = threadIdx.x;
    __shared__ float red[256];
    __shared__ float buf[256];

    float cosv = cosp[t * HDIM + d];
    float sinv = sinp[t * HDIM + d];

    for (int hidx = 0; hidx < 5; hidx++) {
        float v = qkv[(long)t * QKVW + hidx * HDIM + d];
        red[d] = v * v; __syncthreads();
        for (int s = 128; s > 0; s >>= 1) { if (d < s) red[d] += red[d + s]; __syncthreads(); }
        float inv = rsqrtf(red[0] / HDIM + 1e-6f);
        const float* w = (hidx < 4) ? qw : kw;
        float xn = v * inv * (1.f + w[d]);
        buf[d] = xn; __syncthreads();
        float rot = (d < 128) ? -buf[d + 128] : buf[d - 128];
        float r = xn * cosv + rot * sinv;
        if (hidx < 4) {
            qout[(long)hidx * TTOK * HDIM + (long)t * HDIM + d] = r;
        } else {
            Kfull[(long)(CCTX + t) * HDIM + d] = r;
            kslice[(long)t * HDIM + d] = r;
        }
        __syncthreads();
    }
    float vv = qkv[(long)t * QKVW + 5 * HDIM + d];
    Vfull[(long)d * STOT + CCTX + t] = vv;
    vslice[(long)d * TTOK + t] = vv;
}

__global__ __launch_bounds__(256) void copy_v_kernel(
    const float* __restrict__ src, float* __restrict__ Vfull)
{
    int idx = blockIdx.x * 256 + threadIdx.x;
    if (idx < HDIM * CCTX) {
        int d = idx / CCTX, s = idx % CCTX;
        Vfull[(long)d * STOT + s] = src[idx];
    }
}

// ---------------------------------------------------------------------------
// softmax with tanh soft-cap + mask
// ---------------------------------------------------------------------------
__global__ __launch_bounds__(256) void softmax_kernel(
    float* __restrict__ sc, const float* __restrict__ mask)
{
    int t = blockIdx.x, h = blockIdx.y;
    float* row = sc + ((long)h * TTOK + t) * STOT;
    const float* mrow = mask + (long)t * STOT;
    __shared__ float red[256];
    int tid = threadIdx.x;
    const float scale = 0.0625f;
    const float invcap = 1.f / 50.f;

    float vals[8];
    float vmax = -1e30f;
#pragma unroll
    for (int j = 0; j < 8; j++) {
        int s = tid + j * 256;
        float v = row[s] * scale;
        v = tanhf(v * invcap) * 50.f + mrow[s];
        vals[j] = v;
        vmax = fmaxf(vmax, v);
    }
    red[tid] = vmax; __syncthreads();
    for (int s = 128; s > 0; s >>= 1) { if (tid < s) red[tid] = fmaxf(red[tid], red[tid + s]); __syncthreads(); }
    float m = red[0]; __syncthreads();
    float lsum = 0.f;
#pragma unroll
    for (int j = 0; j < 8; j++) { vals[j] = expf(vals[j] - m); lsum += vals[j]; }
    red[tid] = lsum; __syncthreads();
    for (int s = 128; s > 0; s >>= 1) { if (tid < s) red[tid] += red[tid + s]; __syncthreads(); }
    float inv = 1.f / red[0];
#pragma unroll
    for (int j = 0; j < 8; j++) row[tid + j * 256] = vals[j] * inv;
}

// ---------------------------------------------------------------------------
// launch
// ---------------------------------------------------------------------------
extern "C" void kernel_launch(void* const* d_in, const int* in_sizes, int n_in,
                              void* d_out, int out_size)
{
    (void)in_sizes; (void)n_in; (void)out_size;
    const float* emb        = (const float*)d_in[0];
    const float* mask_g     = (const float*)d_in[1];
    const float* mask_l     = (const float*)d_in[2];
    const float* pe_cos     = (const float*)d_in[3];
    const float* pe_sin     = (const float*)d_in[4];
    const float* pe_cos_loc = (const float*)d_in[5];
    const float* pe_sin_loc = (const float*)d_in[6];
    const float* kv_k       = (const float*)d_in[7];
    const float* kv_v       = (const float*)d_in[8];
    const float* pre_attn_w = (const float*)d_in[9];
    const float* q_norm_w   = (const float*)d_in[10];
    const float* k_norm_w   = (const float*)d_in[11];
    const float* post_attn_w= (const float*)d_in[12];
    const float* pre_ff_w   = (const float*)d_in[13];
    const float* post_ff_w  = (const float*)d_in[14];
    const float* final_w    = (const float*)d_in[15];
    const float* w_qkv      = (const float*)d_in[16];
    const float* w_out      = (const float*)d_in[17];
    const float* w_gate     = (const float*)d_in[18];
    const float* w_up       = (const float*)d_in[19];
    const float* w_down     = (const float*)d_in[20];
    const float* w_lm       = (const float*)d_in[21];

    float* out    = (float*)d_out;
    float* logits = out;
    float* kout   = out + (long)TTOK * VOCAB;
    float* vout   = kout + (long)LAY * TTOK * HDIM;

    void* sp = nullptr;
    cudaGetSymbolAddress(&sp, g_scratch);
    float* S = (float*)sp;
    float* g_h    = S + OFF_H;
    float* g_x    = S + OFF_X;
    float* g_qkv  = S + OFF_QKV;
    float* g_q    = S + OFF_Q;
    float* g_K    = S + OFF_K;
    float* g_V    = S + OFF_V;
    float* g_sc   = S + OFF_SC;
    float* g_att  = S + OFF_ATT;
    float* g_proj = S + OFF_PROJ;
    float* g_ff1  = S + OFF_FF1;
    float* g_ff2  = S + OFF_FF2;
    float* g_part = S + OFF_PART;

    cudaMemcpyAsync(g_h, emb, (long)TTOK * DMODEL * sizeof(float),
                    cudaMemcpyDeviceToDevice);

    for (int i = 0; i < LAY; i++) {
        bool is_local = ((i + 1) % 6 == 0);
        const float* cosP = is_local ? pe_cos_loc : pe_cos;
        const float* sinP = is_local ? pe_sin_loc : pe_sin;
        const float* mask = is_local ? mask_l : mask_g;

        rms_kernel<<<TTOK, 256>>>(g_h, pre_attn_w + (long)i * DMODEL, g_x, DMODEL);

        // qkv = x @ w_qkv[i] : N=1536 (12 tiles), K=1152, split 6
        gemm_mma<false><<<dim3(QKVW / 128, 6, 1), 256>>>(
            g_x, w_qkv + (long)i * DMODEL * QKVW, g_part,
            DMODEL, DMODEL, QKVW, 0, 12, 0, 0, 0);
        reduce_split<<<dim3(TTOK * QKVW / 1024, 1), 256>>>(g_part, g_qkv, 6, QKVW, QKVW);

        cudaMemcpyAsync(g_K, kv_k + (long)i * CCTX * HDIM,
                        (long)CCTX * HDIM * sizeof(float), cudaMemcpyDeviceToDevice);
        copy_v_kernel<<<(HDIM * CCTX + 255) / 256, 256>>>(
            kv_v + (long)i * HDIM * CCTX, g_V);

        qk_rope_kernel<<<TTOK, 256>>>(
            g_qkv, q_norm_w + (long)i * HDIM, k_norm_w + (long)i * HDIM,
            cosP, sinP, g_q, g_K, g_V,
            kout + (long)i * TTOK * HDIM, vout + (long)i * HDIM * TTOK);

        // scores[h] = q[h] @ K^T : N=2048 (16 tiles) x 4 heads, K=256
        gemm_mma<true><<<dim3(STOT / 128, 1, NHEAD), 256>>>(
            g_q, g_K, g_sc,
            HDIM, HDIM, HDIM, STOT, 16,
            (long)TTOK * HDIM, 0, (long)TTOK * STOT);

        softmax_kernel<<<dim3(TTOK, NHEAD), 256>>>(g_sc, mask);

        // att[h] = attn[h] @ V^T : N=256 (2 tiles) x 4 heads, K=2048, split 8
        gemm_mma<true><<<dim3(HDIM / 128, 8, NHEAD), 256>>>(
            g_sc, g_V, g_part,
            STOT, STOT, STOT, 0, 16,
            (long)TTOK * STOT, 0, 0);
        reduce_split<<<dim3(TTOK * HDIM / 1024, NHEAD), 256>>>(
            g_part, g_att, 8, HDIM, NHEAD * HDIM);

        // proj = att @ w_out[i] : N=1152 (9 tiles), K=1024, split 8
        gemm_mma<false><<<dim3(DMODEL / 128, 8, 1), 256>>>(
            g_att, w_out + (long)i * (NHEAD * HDIM) * DMODEL, g_part,
            NHEAD * HDIM, NHEAD * HDIM, DMODEL, 0, 8, 0, 0, 0);
        reduce_split<<<dim3(TTOK * DMODEL / 1024, 1), 256>>>(g_part, g_proj, 8, DMODEL, DMODEL);

        add_rms_kernel<<<TTOK, 256>>>(g_h, g_proj, post_attn_w + (long)i * DMODEL, DMODEL);

        rms_kernel<<<TTOK, 256>>>(g_h, pre_ff_w + (long)i * DMODEL, g_x, DMODEL);

        // gate : N=6912 (54 tiles), K=1152, split 2
        gemm_mma<false><<<dim3(FFDIM / 128, 2, 1), 256>>>(
            g_x, w_gate + (long)i * DMODEL * FFDIM, g_part,
            DMODEL, DMODEL, FFDIM, 0, 36, 0, 0, 0);
        reduce_split<<<dim3(TTOK * FFDIM / 1024, 1), 256>>>(g_part, g_ff2, 2, FFDIM, FFDIM);

        // up : split 2 ; then ff1 = gelu(gate) * up (fused)
        gemm_mma<false><<<dim3(FFDIM / 128, 2, 1), 256>>>(
            g_x, w_up + (long)i * DMODEL * FFDIM, g_part,
            DMODEL, DMODEL, FFDIM, 0, 36, 0, 0, 0);
        reduce_split_gelu<<<dim3(TTOK * FFDIM / 1024, 1), 256>>>(
            g_part, g_ff2, g_ff1, 2, FFDIM);

        // down : N=1152 (9 tiles), K=6912, split 8
        gemm_mma<false><<<dim3(DMODEL / 128, 8, 1), 256>>>(
            g_ff1, w_down + (long)i * FFDIM * DMODEL, g_part,
            FFDIM, FFDIM, DMODEL, 0, 54, 0, 0, 0);
        reduce_split<<<dim3(TTOK * DMODEL / 1024, 1), 256>>>(g_part, g_proj, 8, DMODEL, DMODEL);

        add_rms_kernel<<<TTOK, 256>>>(g_h, g_proj, post_ff_w + (long)i * DMODEL, DMODEL);
    }

    rms_kernel<<<TTOK, 256>>>(g_h, final_w, g_x, DMODEL);
    // lm head : N=32768 (256 tiles), K=1152, no split
    gemm_mma<false><<<dim3(VOCAB / 128, 1, 1), 256>>>(
        g_x, w_lm, logits,
        DMODEL, DMODEL, VOCAB, VOCAB, 72, 0, 0, 0);
}

// round 7
// speedup vs baseline: 1.9302x; 1.9302x over previous
#include <cuda_runtime.h>
#include <cuda_bf16.h>
#include <math.h>
#include <stdint.h>

// ---------------------------------------------------------------------------
// Gemma3 prefill forward — Round 6: mma.sync bf16 hi/lo GEMMs, ldmatrix
// fragment loads + vectorized conversion/stores (fixes R5 issue-boundness).
// ---------------------------------------------------------------------------

#define LAY    12
#define DMODEL 1152
#define NHEAD  4
#define HDIM   256
#define FFDIM  6912
#define VOCAB  32768
#define TTOK   128
#define CCTX   1920
#define STOT   2048
#define QKVW   1536   // (NH+2)*HD

// ---- scratch (single device global, no allocations) ----
#define OFF_H     0
#define OFF_X     (OFF_H + TTOK*DMODEL)
#define OFF_QKV   (OFF_X + TTOK*DMODEL)
#define OFF_Q     (OFF_QKV + TTOK*QKVW)
#define OFF_K     (OFF_Q + NHEAD*TTOK*HDIM)
#define OFF_V     (OFF_K + STOT*HDIM)
#define OFF_SC    (OFF_V + HDIM*STOT)
#define OFF_ATT   (OFF_SC + NHEAD*TTOK*STOT)
#define OFF_PROJ  (OFF_ATT + TTOK*NHEAD*HDIM)
#define OFF_FF1   (OFF_PROJ + TTOK*DMODEL)
#define OFF_FF2   (OFF_FF1 + TTOK*FFDIM)
#define OFF_PART  (OFF_FF2 + TTOK*FFDIM)
#define PART_MAX  (2*TTOK*FFDIM)
#define SCRATCH_TOTAL (OFF_PART + PART_MAX)

__device__ float g_scratch[SCRATCH_TOTAL];

// ---------------------------------------------------------------------------
// helpers
// ---------------------------------------------------------------------------
__device__ __forceinline__ void mma16816(float* c, const uint32_t* a,
                                         uint32_t b0, uint32_t b1) {
    asm volatile(
        "mma.sync.aligned.m16n8k16.row.col.f32.bf16.bf16.f32 "
        "{%0,%1,%2,%3}, {%4,%5,%6,%7}, {%8,%9}, {%0,%1,%2,%3};"
        : "+f"(c[0]), "+f"(c[1]), "+f"(c[2]), "+f"(c[3])
        : "r"(a[0]), "r"(a[1]), "r"(a[2]), "r"(a[3]), "r"(b0), "r"(b1));
}

__device__ __forceinline__ void ldm4(uint32_t* r, const __nv_bfloat16* p) {
    uint32_t a = (uint32_t)__cvta_generic_to_shared(p);
    asm volatile("ldmatrix.sync.aligned.m8n8.x4.shared.b16 {%0,%1,%2,%3}, [%4];"
                 : "=r"(r[0]), "=r"(r[1]), "=r"(r[2]), "=r"(r[3]) : "r"(a));
}

// hi = truncated-bf16 pair (PRMT of high halves); lo = bf16(x - hi) pair.
// x = hi + lo holds to ~2^-16 relative.
__device__ __forceinline__ void cvt_pair(float x0, float x1,
                                         uint32_t& hi2, uint32_t& lo2) {
    uint32_t u0 = __float_as_uint(x0), u1 = __float_as_uint(x1);
    hi2 = __byte_perm(u0, u1, 0x7632);              // {bf16(x0), bf16(x1)} trunc
    float h0 = __uint_as_float(u0 & 0xFFFF0000u);
    float h1 = __uint_as_float(u1 & 0xFFFF0000u);
    float l0 = x0 - h0, l1 = x1 - h1;               // exact residuals
    asm("cvt.rn.bf16x2.f32 %0, %1, %2;" : "=r"(lo2) : "f"(l1), "f"(l0));
}

__device__ __forceinline__ void cvt8(const float* f, uint32_t* hi, uint32_t* lo) {
#pragma unroll
    for (int p = 0; p < 4; p++) cvt_pair(f[2*p], f[2*p+1], hi[p], lo[p]);
}

// ---------------------------------------------------------------------------
// GEMM: C[128, N] = A[128,K] @ B   (BT=0: B KxN row-major; BT=1: B NxK, A@B^T)
// CTA 128x128, 256 threads (8 warps, warp tile 32x64), k-chunk 16.
// smem rows padded to 24 bf16 (conflict-free ldmatrix).
// grid = (N/128, split, batch); split>1 -> dense partials [batch][z][128][Nt].
// ---------------------------------------------------------------------------
#define KPAD 24

template<bool BT>
__global__ __launch_bounds__(256) void gemm_mma(
    const float* __restrict__ A, const float* __restrict__ B, float* __restrict__ C,
    int K, int lda, int ldb, int ldc, int ktiles_split,
    long sA, long sB, long sC)
{
    __shared__ __nv_bfloat16 As[2][128 * KPAD];   // [hi/lo][m][k]
    __shared__ __nv_bfloat16 Bs[2][128 * KPAD];   // [hi/lo][n][k]

    const int tid = threadIdx.x;
    const int bz = blockIdx.z, z = blockIdx.y;
    const int bn = blockIdx.x * 128;

    const float* Ab = A + (long)bz * sA;
    const float* Bb = B + (long)bz * sB;

    const int ktot = K >> 4;
    const int kb   = z * ktiles_split;
    const int nkt  = min(ktiles_split, ktot - kb);

    // global-load indexing
    const int arow = tid >> 1, akc = (tid & 1) * 8;   // A and BT-B: 8 k-contig
    const int bnn  = tid & 127, bkg = tid >> 7;       // NN-B: 8 k-contig at col n

    float af[8], bf[8];
    {
        const float* ap = Ab + (long)arow * lda + kb * 16 + akc;
        *(float4*)&af[0] = *(const float4*)ap;
        *(float4*)&af[4] = *(const float4*)(ap + 4);
        if (BT) {
            const float* bp = Bb + (long)(bn + arow) * ldb + kb * 16 + akc;
            *(float4*)&bf[0] = *(const float4*)bp;
            *(float4*)&bf[4] = *(const float4*)(bp + 4);
        } else {
#pragma unroll
            for (int j = 0; j < 8; j++)
                bf[j] = Bb[(long)(kb * 16 + bkg * 8 + j) * ldb + bn + bnn];
        }
    }

    float acc[2][8][4];
#pragma unroll
    for (int i = 0; i < 2; i++)
#pragma unroll
        for (int j = 0; j < 8; j++)
#pragma unroll
            for (int l = 0; l < 4; l++) acc[i][j][l] = 0.f;

    const int w = tid >> 5, lane = tid & 31;
    const int wm = (w & 3) * 32, wn = (w >> 2) * 64;
    const int r = lane >> 2, cp = (lane & 3) * 2;
    const int grp = lane >> 3, rr = lane & 7;

    for (int kt = 0; kt < nkt; kt++) {
        // ---- commit prefetched tile (vectorized hi/lo convert + STS.128) ----
        {
            uint32_t hi[4], lo[4];
            cvt8(af, hi, lo);
            *(uint4*)&As[0][arow * KPAD + akc] = make_uint4(hi[0], hi[1], hi[2], hi[3]);
            *(uint4*)&As[1][arow * KPAD + akc] = make_uint4(lo[0], lo[1], lo[2], lo[3]);
            cvt8(bf, hi, lo);
            if (BT) {
                *(uint4*)&Bs[0][arow * KPAD + akc] = make_uint4(hi[0], hi[1], hi[2], hi[3]);
                *(uint4*)&Bs[1][arow * KPAD + akc] = make_uint4(lo[0], lo[1], lo[2], lo[3]);
            } else {
                *(uint4*)&Bs[0][bnn * KPAD + bkg * 8] = make_uint4(hi[0], hi[1], hi[2], hi[3]);
                *(uint4*)&Bs[1][bnn * KPAD + bkg * 8] = make_uint4(lo[0], lo[1], lo[2], lo[3]);
            }
        }
        __syncthreads();

        // ---- prefetch next tile ----
        if (kt + 1 < nkt) {
            const int k0 = (kb + kt + 1) * 16;
            const float* ap = Ab + (long)arow * lda + k0 + akc;
            *(float4*)&af[0] = *(const float4*)ap;
            *(float4*)&af[4] = *(const float4*)(ap + 4);
            if (BT) {
                const float* bp = Bb + (long)(bn + arow) * ldb + k0 + akc;
                *(float4*)&bf[0] = *(const float4*)bp;
                *(float4*)&bf[4] = *(const float4*)(bp + 4);
            } else {
#pragma unroll
                for (int j = 0; j < 8; j++)
                    bf[j] = Bb[(long)(k0 + bkg * 8 + j) * ldb + bn + bnn];
            }
        }

        // ---- ldmatrix fragments ----
        uint32_t afr[2][2][4];        // [hi/lo][mf][4]
#pragma unroll
        for (int h = 0; h < 2; h++)
#pragma unroll
            for (int mf = 0; mf < 2; mf++) {
                int row = wm + mf * 16 + (grp & 1) * 8 + rr;
                int col = (grp >> 1) * 8;
                ldm4(afr[h][mf], &As[h][row * KPAD + col]);
            }
        uint32_t bfr[2][4][4];        // [hi/lo][nfp][4] : r0,r1 = nf even; r2,r3 = nf odd
#pragma unroll
        for (int h = 0; h < 2; h++)
#pragma unroll
            for (int nfp = 0; nfp < 4; nfp++) {
                int row = wn + nfp * 16 + (grp >> 1) * 8 + rr;
                int col = (grp & 1) * 8;
                ldm4(bfr[h][nfp], &Bs[h][row * KPAD + col]);
            }

        // ---- mma: hi*hi + lo*hi + hi*lo ----
#pragma unroll
        for (int nfp = 0; nfp < 4; nfp++)
#pragma unroll
            for (int sub = 0; sub < 2; sub++) {
                int nf = nfp * 2 + sub;
                uint32_t bh0 = bfr[0][nfp][sub * 2], bh1 = bfr[0][nfp][sub * 2 + 1];
                uint32_t bl0 = bfr[1][nfp][sub * 2], bl1 = bfr[1][nfp][sub * 2 + 1];
#pragma unroll
                for (int mf = 0; mf < 2; mf++) {
                    mma16816(acc[mf][nf], afr[0][mf], bh0, bh1);
                    mma16816(acc[mf][nf], afr[1][mf], bh0, bh1);
                    mma16816(acc[mf][nf], afr[0][mf], bl0, bl1);
                }
            }
        __syncthreads();
    }

    // ---- writeback ----
    const int Nt = gridDim.x * 128;
    const bool direct = (gridDim.y == 1);
#pragma unroll
    for (int mf = 0; mf < 2; mf++)
#pragma unroll
        for (int nf = 0; nf < 8; nf++) {
            int row = wm + mf * 16 + r;
            int col = bn + wn + nf * 8 + cp;
            float* c = acc[mf][nf];
            if (direct) {
                float* p = C + (long)bz * sC + (long)row * ldc + col;
                *(float2*)p = make_float2(c[0], c[1]);
                *(float2*)(p + 8LL * ldc) = make_float2(c[2], c[3]);
            } else {
                float* p = C + ((long)(bz * gridDim.y + z) * 128 + row) * Nt + col;
                *(float2*)p = make_float2(c[0], c[1]);
                *(float2*)(p + 8LL * Nt) = make_float2(c[2], c[3]);
            }
        }
}

// Sum split-K partials: C[m*ldc + bz*Npart + n] = sum_s P[bz][s][m][n]
__global__ __launch_bounds__(256) void reduce_split(
    const float* __restrict__ P, float* __restrict__ C,
    int split, int Npart, int ldc)
{
    int bz = blockIdx.y;
    long idx = ((long)blockIdx.x * 256 + threadIdx.x) * 4;
    int m = (int)(idx / Npart);
    int n = (int)(idx % Npart);
    const float* base = P + (long)bz * split * TTOK * Npart + (long)m * Npart + n;
    float4 s = *(const float4*)base;
    for (int t = 1; t < split; t++) {
        float4 v = *(const float4*)(base + (long)t * TTOK * Npart);
        s.x += v.x; s.y += v.y; s.z += v.z; s.w += v.w;
    }
    *(float4*)(C + (long)m * ldc + bz * Npart + n) = s;
}

__device__ __forceinline__ float gelu_t(float x) {
    float x3 = x * x * x;
    return 0.5f * x * (1.f + tanhf(0.7978845608028654f * (x + 0.044715f * x3)));
}

// Reduce "up" partials, then out = gelu(gate) * up
__global__ __launch_bounds__(256) void reduce_split_gelu(
    const float* __restrict__ P, const float* __restrict__ G,
    float* __restrict__ C, int split, int Npart)
{
    long idx = ((long)blockIdx.x * 256 + threadIdx.x) * 4;
    const float* base = P + idx;
    float4 s = *(const float4*)base;
    for (int t = 1; t < split; t++) {
        float4 v = *(const float4*)(base + (long)t * TTOK * Npart);
        s.x += v.x; s.y += v.y; s.z += v.z; s.w += v.w;
    }
    float4 g = *(const float4*)(G + idx);
    s.x *= gelu_t(g.x); s.y *= gelu_t(g.y);
    s.z *= gelu_t(g.z); s.w *= gelu_t(g.w);
    *(float4*)(C + idx) = s;
}

// ---------------------------------------------------------------------------
// RMSNorm kernels
// ---------------------------------------------------------------------------
__global__ __launch_bounds__(256) void rms_kernel(
    const float* __restrict__ x, const float* __restrict__ w,
    float* __restrict__ y, int ncols)
{
    int row = blockIdx.x;
    const float* xr = x + (long)row * ncols;
    __shared__ float red[256];
    int tid = threadIdx.x;
    float ss = 0.f;
    for (int c = tid; c < ncols; c += 256) { float v = xr[c]; ss += v * v; }
    red[tid] = ss; __syncthreads();
    for (int s = 128; s > 0; s >>= 1) { if (tid < s) red[tid] += red[tid + s]; __syncthreads(); }
    float inv = rsqrtf(red[0] / ncols + 1e-6f);
    for (int c = tid; c < ncols; c += 256)
        y[(long)row * ncols + c] = xr[c] * inv * (1.f + w[c]);
}

__global__ __launch_bounds__(256) void add_rms_kernel(
    float* __restrict__ h, const float* __restrict__ p,
    const float* __restrict__ w, int ncols)
{
    int row = blockIdx.x;
    const float* pr = p + (long)row * ncols;
    __shared__ float red[256];
    int tid = threadIdx.x;
    float ss = 0.f;
    for (int c = tid; c < ncols; c += 256) { float v = pr[c]; ss += v * v; }
    red[tid] = ss; __syncthreads();
    for (int s = 128; s > 0; s >>= 1) { if (tid < s) red[tid] += red[tid + s]; __syncthreads(); }
    float inv = rsqrtf(red[0] / ncols + 1e-6f);
    for (int c = tid; c < ncols; c += 256)
        h[(long)row * ncols + c] += pr[c] * inv * (1.f + w[c]);
}

// ---------------------------------------------------------------------------
// Q/K rmsnorm + RoPE + V scatter
// ---------------------------------------------------------------------------
__global__ __launch_bounds__(256) void qk_rope_kernel(
    const float* __restrict__ qkv,
    const float* __restrict__ qw, const float* __restrict__ kw,
    const float* __restrict__ cosp, const float* __restrict__ sinp,
    float* __restrict__ qout, float* __restrict__ Kfull, float* __restrict__ Vfull,
    float* __restrict__ kslice, float* __restrict__ vslice)
{
    int t = blockIdx.x;
    int d = threadIdx.x;
    __shared__ float red[256];
    __shared__ float buf[256];

    float cosv = cosp[t * HDIM + d];
    float sinv = sinp[t * HDIM + d];

    for (int hidx = 0; hidx < 5; hidx++) {
        float v = qkv[(long)t * QKVW + hidx * HDIM + d];
        red[d] = v * v; __syncthreads();
        for (int s = 128; s > 0; s >>= 1) { if (d < s) red[d] += red[d + s]; __syncthreads(); }
        float inv = rsqrtf(red[0] / HDIM + 1e-6f);
        const float* w = (hidx < 4) ? qw : kw;
        float xn = v * inv * (1.f + w[d]);
        buf[d] = xn; __syncthreads();
        float rot = (d < 128) ? -buf[d + 128] : buf[d - 128];
        float r = xn * cosv + rot * sinv;
        if (hidx < 4) {
            qout[(long)hidx * TTOK * HDIM + (long)t * HDIM + d] = r;
        } else {
            Kfull[(long)(CCTX + t) * HDIM + d] = r;
            kslice[(long)t * HDIM + d] = r;
        }
        __syncthreads();
    }
    float vv = qkv[(long)t * QKVW + 5 * HDIM + d];
    Vfull[(long)d * STOT + CCTX + t] = vv;
    vslice[(long)d * TTOK + t] = vv;
}

__global__ __launch_bounds__(256) void copy_v_kernel(
    const float* __restrict__ src, float* __restrict__ Vfull)
{
    int idx = blockIdx.x * 256 + threadIdx.x;
    if (idx < HDIM * CCTX) {
        int d = idx / CCTX, s = idx % CCTX;
        Vfull[(long)d * STOT + s] = src[idx];
    }
}

// ---------------------------------------------------------------------------
// softmax with tanh soft-cap + mask
// ---------------------------------------------------------------------------
__global__ __launch_bounds__(256) void softmax_kernel(
    float* __restrict__ sc, const float* __restrict__ mask)
{
    int t = blockIdx.x, h = blockIdx.y;
    float* row = sc + ((long)h * TTOK + t) * STOT;
    const float* mrow = mask + (long)t * STOT;
    __shared__ float red[256];
    int tid = threadIdx.x;
    const float scale = 0.0625f;
    const float invcap = 1.f / 50.f;

    float vals[8];
    float vmax = -1e30f;
#pragma unroll
    for (int j = 0; j < 8; j++) {
        int s = tid + j * 256;
        float v = row[s] * scale;
        v = tanhf(v * invcap) * 50.f + mrow[s];
        vals[j] = v;
        vmax = fmaxf(vmax, v);
    }
    red[tid] = vmax; __syncthreads();
    for (int s = 128; s > 0; s >>= 1) { if (tid < s) red[tid] = fmaxf(red[tid], red[tid + s]); __syncthreads(); }
    float m = red[0]; __syncthreads();
    float lsum = 0.f;
#pragma unroll
    for (int j = 0; j < 8; j++) { vals[j] = expf(vals[j] - m); lsum += vals[j]; }
    red[tid] = lsum; __syncthreads();
    for (int s = 128; s > 0; s >>= 1) { if (tid < s) red[tid] += red[tid + s]; __syncthreads(); }
    float inv = 1.f / red[0];
#pragma unroll
    for (int j = 0; j < 8; j++) row[tid + j * 256] = vals[j] * inv;
}

// ---------------------------------------------------------------------------
// launch
// ---------------------------------------------------------------------------
extern "C" void kernel_launch(void* const* d_in, const int* in_sizes, int n_in,
                              void* d_out, int out_size)
{
    (void)in_sizes; (void)n_in; (void)out_size;
    const float* emb        = (const float*)d_in[0];
    const float* mask_g     = (const float*)d_in[1];
    const float* mask_l     = (const float*)d_in[2];
    const float* pe_cos     = (const float*)d_in[3];
    const float* pe_sin     = (const float*)d_in[4];
    const float* pe_cos_loc = (const float*)d_in[5];
    const float* pe_sin_loc = (const float*)d_in[6];
    const float* kv_k       = (const float*)d_in[7];
    const float* kv_v       = (const float*)d_in[8];
    const float* pre_attn_w = (const float*)d_in[9];
    const float* q_norm_w   = (const float*)d_in[10];
    const float* k_norm_w   = (const float*)d_in[11];
    const float* post_attn_w= (const float*)d_in[12];
    const float* pre_ff_w   = (const float*)d_in[13];
    const float* post_ff_w  = (const float*)d_in[14];
    const float* final_w    = (const float*)d_in[15];
    const float* w_qkv      = (const float*)d_in[16];
    const float* w_out      = (const float*)d_in[17];
    const float* w_gate     = (const float*)d_in[18];
    const float* w_up       = (const float*)d_in[19];
    const float* w_down     = (const float*)d_in[20];
    const float* w_lm       = (const float*)d_in[21];

    float* out    = (float*)d_out;
    float* logits = out;
    float* kout   = out + (long)TTOK * VOCAB;
    float* vout   = kout + (long)LAY * TTOK * HDIM;

    void* sp = nullptr;
    cudaGetSymbolAddress(&sp, g_scratch);
    float* S = (float*)sp;
    float* g_h    = S + OFF_H;
    float* g_x    = S + OFF_X;
    float* g_qkv  = S + OFF_QKV;
    float* g_q    = S + OFF_Q;
    float* g_K    = S + OFF_K;
    float* g_V    = S + OFF_V;
    float* g_sc   = S + OFF_SC;
    float* g_att  = S + OFF_ATT;
    float* g_proj = S + OFF_PROJ;
    float* g_ff1  = S + OFF_FF1;
    float* g_ff2  = S + OFF_FF2;
    float* g_part = S + OFF_PART;

    cudaMemcpyAsync(g_h, emb, (long)TTOK * DMODEL * sizeof(float),
                    cudaMemcpyDeviceToDevice);

    for (int i = 0; i < LAY; i++) {
        bool is_local = ((i + 1) % 6 == 0);
        const float* cosP = is_local ? pe_cos_loc : pe_cos;
        const float* sinP = is_local ? pe_sin_loc : pe_sin;
        const float* mask = is_local ? mask_l : mask_g;

        rms_kernel<<<TTOK, 256>>>(g_h, pre_attn_w + (long)i * DMODEL, g_x, DMODEL);

        // qkv = x @ w_qkv[i] : N=1536 (12 tiles), K=1152, split 6
        gemm_mma<false><<<dim3(QKVW / 128, 6, 1), 256>>>(
            g_x, w_qkv + (long)i * DMODEL * QKVW, g_part,
            DMODEL, DMODEL, QKVW, 0, 12, 0, 0, 0);
        reduce_split<<<dim3(TTOK * QKVW / 1024, 1), 256>>>(g_part, g_qkv, 6, QKVW, QKVW);

        cudaMemcpyAsync(g_K, kv_k + (long)i * CCTX * HDIM,
                        (long)CCTX * HDIM * sizeof(float), cudaMemcpyDeviceToDevice);
        copy_v_kernel<<<(HDIM * CCTX + 255) / 256, 256>>>(
            kv_v + (long)i * HDIM * CCTX, g_V);

        qk_rope_kernel<<<TTOK, 256>>>(
            g_qkv, q_norm_w + (long)i * HDIM, k_norm_w + (long)i * HDIM,
            cosP, sinP, g_q, g_K, g_V,
            kout + (long)i * TTOK * HDIM, vout + (long)i * HDIM * TTOK);

        // scores[h] = q[h] @ K^T : N=2048 (16 tiles) x 4 heads, K=256
        gemm_mma<true><<<dim3(STOT / 128, 1, NHEAD), 256>>>(
            g_q, g_K, g_sc,
            HDIM, HDIM, HDIM, STOT, 16,
            (long)TTOK * HDIM, 0, (long)TTOK * STOT);

        softmax_kernel<<<dim3(TTOK, NHEAD), 256>>>(g_sc, mask);

        // att[h] = attn[h] @ V^T : N=256 (2 tiles) x 4 heads, K=2048, split 8
        gemm_mma<true><<<dim3(HDIM / 128, 8, NHEAD), 256>>>(
            g_sc, g_V, g_part,
            STOT, STOT, STOT, 0, 16,
            (long)TTOK * STOT, 0, 0);
        reduce_split<<<dim3(TTOK * HDIM / 1024, NHEAD), 256>>>(
            g_part, g_att, 8, HDIM, NHEAD * HDIM);

        // proj = att @ w_out[i] : N=1152 (9 tiles), K=1024, split 8
        gemm_mma<false><<<dim3(DMODEL / 128, 8, 1), 256>>>(
            g_att, w_out + (long)i * (NHEAD * HDIM) * DMODEL, g_part,
            NHEAD * HDIM, NHEAD * HDIM, DMODEL, 0, 8, 0, 0, 0);
        reduce_split<<<dim3(TTOK * DMODEL / 1024, 1), 256>>>(g_part, g_proj, 8, DMODEL, DMODEL);

        add_rms_kernel<<<TTOK, 256>>>(g_h, g_proj, post_attn_w + (long)i * DMODEL, DMODEL);

        rms_kernel<<<TTOK, 256>>>(g_h, pre_ff_w + (long)i * DMODEL, g_x, DMODEL);

        // gate : N=6912 (54 tiles), K=1152, split 2
        gemm_mma<false><<<dim3(FFDIM / 128, 2, 1), 256>>>(
            g_x, w_gate + (long)i * DMODEL * FFDIM, g_part,
            DMODEL, DMODEL, FFDIM, 0, 36, 0, 0, 0);
        reduce_split<<<dim3(TTOK * FFDIM / 1024, 1), 256>>>(g_part, g_ff2, 2, FFDIM, FFDIM);

        // up : split 2 ; then ff1 = gelu(gate) * up (fused)
        gemm_mma<false><<<dim3(FFDIM / 128, 2, 1), 256>>>(
            g_x, w_up + (long)i * DMODEL * FFDIM, g_part,
            DMODEL, DMODEL, FFDIM, 0, 36, 0, 0, 0);
        reduce_split_gelu<<<dim3(TTOK * FFDIM / 1024, 1), 256>>>(
            g_part, g_ff2, g_ff1, 2, FFDIM);

        // down : N=1152 (9 tiles), K=6912, split 8
        gemm_mma<false><<<dim3(DMODEL / 128, 8, 1), 256>>>(
            g_ff1, w_down + (long)i * FFDIM * DMODEL, g_part,
            FFDIM, FFDIM, DMODEL, 0, 54, 0, 0, 0);
        reduce_split<<<dim3(TTOK * DMODEL / 1024, 1), 256>>>(g_part, g_proj, 8, DMODEL, DMODEL);

        add_rms_kernel<<<TTOK, 256>>>(g_h, g_proj, post_ff_w + (long)i * DMODEL, DMODEL);
    }

    rms_kernel<<<TTOK, 256>>>(g_h, final_w, g_x, DMODEL);
    // lm head : N=32768 (256 tiles), K=1152, no split
    gemm_mma<false><<<dim3(VOCAB / 128, 1, 1), 256>>>(
        g_x, w_lm, logits,
        DMODEL, DMODEL, VOCAB, VOCAB, 72, 0, 0, 0);
}

// round 8
// speedup vs baseline: 1.9553x; 1.0130x over previous
#include <cuda_runtime.h>
#include <cuda_bf16.h>
#include <math.h>
#include <stdint.h>

// ---------------------------------------------------------------------------
// Gemma3 prefill forward — Round 7: combo-major MMA ordering + kernel fusion
// + fast transcendentals.  (bf16 hi/lo mma.sync GEMMs, split-K partials.)
// ---------------------------------------------------------------------------

#define LAY    12
#define DMODEL 1152
#define NHEAD  4
#define HDIM   256
#define FFDIM  6912
#define VOCAB  32768
#define TTOK   128
#define CCTX   1920
#define STOT   2048
#define QKVW   1536   // (NH+2)*HD

// ---- scratch (single device global, no allocations) ----
#define OFF_H     0
#define OFF_X     (OFF_H + TTOK*DMODEL)
#define OFF_Q     (OFF_X + TTOK*DMODEL)
#define OFF_K     (OFF_Q + NHEAD*TTOK*HDIM)
#define OFF_V     (OFF_K + STOT*HDIM)
#define OFF_SC    (OFF_V + HDIM*STOT)
#define OFF_ATT   (OFF_SC + NHEAD*TTOK*STOT)
#define OFF_PROJ  (OFF_ATT + TTOK*NHEAD*HDIM)
#define OFF_FF1   (OFF_PROJ + TTOK*DMODEL)
#define OFF_PART  (OFF_FF1 + TTOK*FFDIM)
#define OFF_PART2 (OFF_PART + 8*TTOK*STOT)      // >= all split-8 partial sets
#define SCRATCH_TOTAL (OFF_PART2 + 2*TTOK*FFDIM)

__device__ float g_scratch[SCRATCH_TOTAL];

// ---------------------------------------------------------------------------
// helpers
// ---------------------------------------------------------------------------
__device__ __forceinline__ void mma16816(float* c, const uint32_t* a,
                                         uint32_t b0, uint32_t b1) {
    asm volatile(
        "mma.sync.aligned.m16n8k16.row.col.f32.bf16.bf16.f32 "
        "{%0,%1,%2,%3}, {%4,%5,%6,%7}, {%8,%9}, {%0,%1,%2,%3};"
        : "+f"(c[0]), "+f"(c[1]), "+f"(c[2]), "+f"(c[3])
        : "r"(a[0]), "r"(a[1]), "r"(a[2]), "r"(a[3]), "r"(b0), "r"(b1));
}

__device__ __forceinline__ void ldm4(uint32_t* r, const __nv_bfloat16* p) {
    uint32_t a = (uint32_t)__cvta_generic_to_shared(p);
    asm volatile("ldmatrix.sync.aligned.m8n8.x4.shared.b16 {%0,%1,%2,%3}, [%4];"
                 : "=r"(r[0]), "=r"(r[1]), "=r"(r[2]), "=r"(r[3]) : "r"(a));
}

// hi = truncated-bf16 pair (PRMT of high halves); lo = bf16(x - hi) pair.
__device__ __forceinline__ void cvt_pair(float x0, float x1,
                                         uint32_t& hi2, uint32_t& lo2) {
    uint32_t u0 = __float_as_uint(x0), u1 = __float_as_uint(x1);
    hi2 = __byte_perm(u0, u1, 0x7632);
    float h0 = __uint_as_float(u0 & 0xFFFF0000u);
    float h1 = __uint_as_float(u1 & 0xFFFF0000u);
    float l0 = x0 - h0, l1 = x1 - h1;
    asm("cvt.rn.bf16x2.f32 %0, %1, %2;" : "=r"(lo2) : "f"(l1), "f"(l0));
}

__device__ __forceinline__ void cvt8(const float* f, uint32_t* hi, uint32_t* lo) {
#pragma unroll
    for (int p = 0; p < 4; p++) cvt_pair(f[2*p], f[2*p+1], hi[p], lo[p]);
}

// saturating fast tanh: 1 - 2/(e^{2x}+1); safe at +-inf
__device__ __forceinline__ float tanh_f(float x) {
    return 1.f - 2.f / (__expf(2.f * x) + 1.f);
}

// ---------------------------------------------------------------------------
// GEMM: C[128, N] = A[128,K] @ B   (BT=0: B KxN row-major; BT=1: B NxK, A@B^T)
// CTA 128x128, 256 threads (8 warps, warp tile 32x64), k-chunk 16,
// smem rows padded to 24 bf16 for conflict-free ldmatrix.
// grid = (N/128, split, batch); split>1 -> dense partials [batch][z][128][Nt].
// ---------------------------------------------------------------------------
#define KPAD 24

template<bool BT>
__global__ __launch_bounds__(256) void gemm_mma(
    const float* __restrict__ A, const float* __restrict__ B, float* __restrict__ C,
    int K, int lda, int ldb, int ldc, int ktiles_split,
    long sA, long sB, long sC)
{
    __shared__ __nv_bfloat16 As[2][128 * KPAD];
    __shared__ __nv_bfloat16 Bs[2][128 * KPAD];

    const int tid = threadIdx.x;
    const int bz = blockIdx.z, z = blockIdx.y;
    const int bn = blockIdx.x * 128;

    const float* Ab = A + (long)bz * sA;
    const float* Bb = B + (long)bz * sB;

    const int ktot = K >> 4;
    const int kb   = z * ktiles_split;
    const int nkt  = min(ktiles_split, ktot - kb);

    const int arow = tid >> 1, akc = (tid & 1) * 8;
    const int bnn  = tid & 127, bkg = tid >> 7;

    float af[8], bf[8];
    {
        const float* ap = Ab + (long)arow * lda + kb * 16 + akc;
        *(float4*)&af[0] = *(const float4*)ap;
        *(float4*)&af[4] = *(const float4*)(ap + 4);
        if (BT) {
            const float* bp = Bb + (long)(bn + arow) * ldb + kb * 16 + akc;
            *(float4*)&bf[0] = *(const float4*)bp;
            *(float4*)&bf[4] = *(const float4*)(bp + 4);
        } else {
#pragma unroll
            for (int j = 0; j < 8; j++)
                bf[j] = Bb[(long)(kb * 16 + bkg * 8 + j) * ldb + bn + bnn];
        }
    }

    float acc[2][8][4];
#pragma unroll
    for (int i = 0; i < 2; i++)
#pragma unroll
        for (int j = 0; j < 8; j++)
#pragma unroll
            for (int l = 0; l < 4; l++) acc[i][j][l] = 0.f;

    const int w = tid >> 5, lane = tid & 31;
    const int wm = (w & 3) * 32, wn = (w >> 2) * 64;
    const int r = lane >> 2, cp = (lane & 3) * 2;
    const int grp = lane >> 3, rr = lane & 7;

    for (int kt = 0; kt < nkt; kt++) {
        {
            uint32_t hi[4], lo[4];
            cvt8(af, hi, lo);
            *(uint4*)&As[0][arow * KPAD + akc] = make_uint4(hi[0], hi[1], hi[2], hi[3]);
            *(uint4*)&As[1][arow * KPAD + akc] = make_uint4(lo[0], lo[1], lo[2], lo[3]);
            cvt8(bf, hi, lo);
            if (BT) {
                *(uint4*)&Bs[0][arow * KPAD + akc] = make_uint4(hi[0], hi[1], hi[2], hi[3]);
                *(uint4*)&Bs[1][arow * KPAD + akc] = make_uint4(lo[0], lo[1], lo[2], lo[3]);
            } else {
                *(uint4*)&Bs[0][bnn * KPAD + bkg * 8] = make_uint4(hi[0], hi[1], hi[2], hi[3]);
                *(uint4*)&Bs[1][bnn * KPAD + bkg * 8] = make_uint4(lo[0], lo[1], lo[2], lo[3]);
            }
        }
        __syncthreads();

        if (kt + 1 < nkt) {
            const int k0 = (kb + kt + 1) * 16;
            const float* ap = Ab + (long)arow * lda + k0 + akc;
            *(float4*)&af[0] = *(const float4*)ap;
            *(float4*)&af[4] = *(const float4*)(ap + 4);
            if (BT) {
                const float* bp = Bb + (long)(bn + arow) * ldb + k0 + akc;
                *(float4*)&bf[0] = *(const float4*)bp;
                *(float4*)&bf[4] = *(const float4*)(bp + 4);
            } else {
#pragma unroll
                for (int j = 0; j < 8; j++)
                    bf[j] = Bb[(long)(k0 + bkg * 8 + j) * ldb + bn + bnn];
            }
        }

        uint32_t afr[2][2][4];
#pragma unroll
        for (int h = 0; h < 2; h++)
#pragma unroll
            for (int mf = 0; mf < 2; mf++) {
                int row = wm + mf * 16 + (grp & 1) * 8 + rr;
                int col = (grp >> 1) * 8;
                ldm4(afr[h][mf], &As[h][row * KPAD + col]);
            }
        uint32_t bfr[2][4][4];
#pragma unroll
        for (int h = 0; h < 2; h++)
#pragma unroll
            for (int nfp = 0; nfp < 4; nfp++) {
                int row = wn + nfp * 16 + (grp >> 1) * 8 + rr;
                int col = (grp & 1) * 8;
                ldm4(bfr[h][nfp], &Bs[h][row * KPAD + col]);
            }

        // ---- combo-major mma: hi*hi, then lo*hi, then hi*lo ----
#pragma unroll
        for (int c = 0; c < 3; c++) {
            const int ha = (c == 1) ? 1 : 0;
            const int hb = (c == 2) ? 1 : 0;
#pragma unroll
            for (int nfp = 0; nfp < 4; nfp++)
#pragma unroll
                for (int sub = 0; sub < 2; sub++) {
                    int nf = nfp * 2 + sub;
                    uint32_t b0 = bfr[hb][nfp][sub * 2];
                    uint32_t b1 = bfr[hb][nfp][sub * 2 + 1];
                    mma16816(acc[0][nf], afr[ha][0], b0, b1);
                    mma16816(acc[1][nf], afr[ha][1], b0, b1);
                }
        }
        __syncthreads();
    }

    const int Nt = gridDim.x * 128;
    const bool direct = (gridDim.y == 1);
#pragma unroll
    for (int mf = 0; mf < 2; mf++)
#pragma unroll
        for (int nf = 0; nf < 8; nf++) {
            int row = wm + mf * 16 + r;
            int col = bn + wn + nf * 8 + cp;
            float* c = acc[mf][nf];
            if (direct) {
                float* p = C + (long)bz * sC + (long)row * ldc + col;
                *(float2*)p = make_float2(c[0], c[1]);
                *(float2*)(p + 8LL * ldc) = make_float2(c[2], c[3]);
            } else {
                float* p = C + ((long)(bz * gridDim.y + z) * 128 + row) * Nt + col;
                *(float2*)p = make_float2(c[0], c[1]);
                *(float2*)(p + 8LL * Nt) = make_float2(c[2], c[3]);
            }
        }
}

// Sum split-K partials: C[m*ldc + bz*Npart + n] = sum_s P[bz][s][m][n]
__global__ __launch_bounds__(256) void reduce_split(
    const float* __restrict__ P, float* __restrict__ C,
    int split, int Npart, int ldc)
{
    int bz = blockIdx.y;
    long idx = ((long)blockIdx.x * 256 + threadIdx.x) * 4;
    int m = (int)(idx / Npart);
    int n = (int)(idx % Npart);
    const float* base = P + (long)bz * split * TTOK * Npart + (long)m * Npart + n;
    float4 s = *(const float4*)base;
    for (int t = 1; t < split; t++) {
        float4 v = *(const float4*)(base + (long)t * TTOK * Npart);
        s.x += v.x; s.y += v.y; s.z += v.z; s.w += v.w;
    }
    *(float4*)(C + (long)m * ldc + bz * Npart + n) = s;
}

__device__ __forceinline__ float gelu_t(float x) {
    float x3 = x * x * x;
    return 0.5f * x * (1.f + tanh_f(0.7978845608028654f * (x + 0.044715f * x3)));
}

// out = gelu(sum Pa) * (sum Pb)  -- both split-2 partial sets
__global__ __launch_bounds__(256) void reduce_gelu_mul(
    const float* __restrict__ Pa, const float* __restrict__ Pb,
    float* __restrict__ C, int split)
{
    long idx = ((long)blockIdx.x * 256 + threadIdx.x) * 4;
    float4 a = *(const float4*)(Pa + idx);
    float4 b = *(const float4*)(Pb + idx);
    for (int t = 1; t < split; t++) {
        float4 va = *(const float4*)(Pa + idx + (long)t * TTOK * FFDIM);
        float4 vb = *(const float4*)(Pb + idx + (long)t * TTOK * FFDIM);
        a.x += va.x; a.y += va.y; a.z += va.z; a.w += va.w;
        b.x += vb.x; b.y += vb.y; b.z += vb.z; b.w += vb.w;
    }
    float4 o;
    o.x = gelu_t(a.x) * b.x; o.y = gelu_t(a.y) * b.y;
    o.z = gelu_t(a.z) * b.z; o.w = gelu_t(a.w) * b.w;
    *(float4*)(C + idx) = o;
}

// ---------------------------------------------------------------------------
// rms (layer-0 entry): y = rms(x, w)
// ---------------------------------------------------------------------------
__global__ __launch_bounds__(256) void rms_kernel(
    const float* __restrict__ x, const float* __restrict__ w,
    float* __restrict__ y, int ncols)
{
    int row = blockIdx.x;
    const float* xr = x + (long)row * ncols;
    __shared__ float red[256];
    int tid = threadIdx.x;
    float ss = 0.f;
    for (int c = tid; c < ncols; c += 256) { float v = xr[c]; ss += v * v; }
    red[tid] = ss; __syncthreads();
    for (int s = 128; s > 0; s >>= 1) { if (tid < s) red[tid] += red[tid + s]; __syncthreads(); }
    float inv = rsqrtf(red[0] / ncols + 1e-6f);
    for (int c = tid; c < ncols; c += 256)
        y[(long)row * ncols + c] = xr[c] * inv * (1.f + w[c]);
}

// ---------------------------------------------------------------------------
// fused: p = sum_z P[z];  h += rms(p, w1);  x = rms(h, w2)
// one block per row (DMODEL=1152 cols, 256 threads)
// ---------------------------------------------------------------------------
__global__ __launch_bounds__(256) void add_rms_rms(
    float* __restrict__ h, const float* __restrict__ P, int split,
    const float* __restrict__ w1, const float* __restrict__ w2,
    float* __restrict__ x)
{
    int row = blockIdx.x, tid = threadIdx.x;
    __shared__ float red[256];
    float pv[5], hv[5];

    float ssp = 0.f;
#pragma unroll
    for (int j = 0; j < 5; j++) {
        int c = tid + j * 256;
        float v = 0.f;
        if (c < DMODEL) {
            const float* b = P + (long)row * DMODEL + c;
            v = b[0];
            for (int t = 1; t < split; t++) v += b[(long)t * TTOK * DMODEL];
        }
        pv[j] = v; ssp += v * v;
    }
    red[tid] = ssp; __syncthreads();
    for (int s = 128; s > 0; s >>= 1) { if (tid < s) red[tid] += red[tid + s]; __syncthreads(); }
    float inv1 = rsqrtf(red[0] / DMODEL + 1e-6f);
    __syncthreads();

    float ssh = 0.f;
#pragma unroll
    for (int j = 0; j < 5; j++) {
        int c = tid + j * 256;
        float v = 0.f;
        if (c < DMODEL) {
            v = h[(long)row * DMODEL + c] + pv[j] * inv1 * (1.f + w1[c]);
            h[(long)row * DMODEL + c] = v;
        }
        hv[j] = v; ssh += v * v;
    }
    red[tid] = ssh; __syncthreads();
    for (int s = 128; s > 0; s >>= 1) { if (tid < s) red[tid] += red[tid + s]; __syncthreads(); }
    float inv2 = rsqrtf(red[0] / DMODEL + 1e-6f);

#pragma unroll
    for (int j = 0; j < 5; j++) {
        int c = tid + j * 256;
        if (c < DMODEL)
            x[(long)row * DMODEL + c] = hv[j] * inv2 * (1.f + w2[c]);
    }
}

// ---------------------------------------------------------------------------
// Q/K rmsnorm + RoPE + V scatter; qkv read as sum of 6 split-K partials
// ---------------------------------------------------------------------------
__global__ __launch_bounds__(256) void qk_rope_kernel(
    const float* __restrict__ P,     // qkv partials [6][128][1536]
    const float* __restrict__ qw, const float* __restrict__ kw,
    const float* __restrict__ cosp, const float* __restrict__ sinp,
    float* __restrict__ qout, float* __restrict__ Kfull, float* __restrict__ Vfull,
    float* __restrict__ kslice, float* __restrict__ vslice)
{
    int t = blockIdx.x;
    int d = threadIdx.x;
    __shared__ float red[256];
    __shared__ float buf[256];

    float cosv = cosp[t * HDIM + d];
    float sinv = sinp[t * HDIM + d];

    for (int hidx = 0; hidx < 5; hidx++) {
        const float* b = P + (long)t * QKVW + hidx * HDIM + d;
        float v = b[0];
#pragma unroll
        for (int zz = 1; zz < 6; zz++) v += b[(long)zz * TTOK * QKVW];
        red[d] = v * v; __syncthreads();
        for (int s = 128; s > 0; s >>= 1) { if (d < s) red[d] += red[d + s]; __syncthreads(); }
        float inv = rsqrtf(red[0] / HDIM + 1e-6f);
        const float* w = (hidx < 4) ? qw : kw;
        float xn = v * inv * (1.f + w[d]);
        buf[d] = xn; __syncthreads();
        float rot = (d < 128) ? -buf[d + 128] : buf[d - 128];
        float r = xn * cosv + rot * sinv;
        if (hidx < 4) {
            qout[(long)hidx * TTOK * HDIM + (long)t * HDIM + d] = r;
        } else {
            Kfull[(long)(CCTX + t) * HDIM + d] = r;
            kslice[(long)t * HDIM + d] = r;
        }
        __syncthreads();
    }
    const float* b = P + (long)t * QKVW + 5 * HDIM + d;
    float vv = b[0];
#pragma unroll
    for (int zz = 1; zz < 6; zz++) vv += b[(long)zz * TTOK * QKVW];
    Vfull[(long)d * STOT + CCTX + t] = vv;
    vslice[(long)d * TTOK + t] = vv;
}

__global__ __launch_bounds__(256) void copy_v_kernel(
    const float* __restrict__ src, float* __restrict__ Vfull)
{
    int idx = blockIdx.x * 256 + threadIdx.x;
    if (idx < HDIM * CCTX) {
        int d = idx / CCTX, s = idx % CCTX;
        Vfull[(long)d * STOT + s] = src[idx];
    }
}

// ---------------------------------------------------------------------------
// softmax with tanh soft-cap + mask (fast transcendentals)
// ---------------------------------------------------------------------------
__global__ __launch_bounds__(256) void softmax_kernel(
    float* __restrict__ sc, const float* __restrict__ mask)
{
    int t = blockIdx.x, h = blockIdx.y;
    float* row = sc + ((long)h * TTOK + t) * STOT;
    const float* mrow = mask + (long)t * STOT;
    __shared__ float red[256];
    int tid = threadIdx.x;
    const float scale = 0.0625f;
    const float invcap = 1.f / 50.f;

    float vals[8];
    float vmax = -1e30f;
#pragma unroll
    for (int j = 0; j < 8; j++) {
        int s = tid + j * 256;
        float v = row[s] * scale;
        v = tanh_f(v * invcap) * 50.f + mrow[s];
        vals[j] = v;
        vmax = fmaxf(vmax, v);
    }
    red[tid] = vmax; __syncthreads();
    for (int s = 128; s > 0; s >>= 1) { if (tid < s) red[tid] = fmaxf(red[tid], red[tid + s]); __syncthreads(); }
    float m = red[0]; __syncthreads();
    float lsum = 0.f;
#pragma unroll
    for (int j = 0; j < 8; j++) { vals[j] = __expf(vals[j] - m); lsum += vals[j]; }
    red[tid] = lsum; __syncthreads();
    for (int s = 128; s > 0; s >>= 1) { if (tid < s) red[tid] += red[tid + s]; __syncthreads(); }
    float inv = 1.f / red[0];
#pragma unroll
    for (int j = 0; j < 8; j++) row[tid + j * 256] = vals[j] * inv;
}

// ---------------------------------------------------------------------------
// launch
// ---------------------------------------------------------------------------
extern "C" void kernel_launch(void* const* d_in, const int* in_sizes, int n_in,
                              void* d_out, int out_size)
{
    (void)in_sizes; (void)n_in; (void)out_size;
    const float* emb        = (const float*)d_in[0];
    const float* mask_g     = (const float*)d_in[1];
    const float* mask_l     = (const float*)d_in[2];
    const float* pe_cos     = (const float*)d_in[3];
    const float* pe_sin     = (const float*)d_in[4];
    const float* pe_cos_loc = (const float*)d_in[5];
    const float* pe_sin_loc = (const float*)d_in[6];
    const float* kv_k       = (const float*)d_in[7];
    const float* kv_v       = (const float*)d_in[8];
    const float* pre_attn_w = (const float*)d_in[9];
    const float* q_norm_w   = (const float*)d_in[10];
    const float* k_norm_w   = (const float*)d_in[11];
    const float* post_attn_w= (const float*)d_in[12];
    const float* pre_ff_w   = (const float*)d_in[13];
    const float* post_ff_w  = (const float*)d_in[14];
    const float* final_w    = (const float*)d_in[15];
    const float* w_qkv      = (const float*)d_in[16];
    const float* w_out      = (const float*)d_in[17];
    const float* w_gate     = (const float*)d_in[18];
    const float* w_up       = (const float*)d_in[19];
    const float* w_down     = (const float*)d_in[20];
    const float* w_lm       = (const float*)d_in[21];

    float* out    = (float*)d_out;
    float* logits = out;
    float* kout   = out + (long)TTOK * VOCAB;
    float* vout   = kout + (long)LAY * TTOK * HDIM;

    void* sp = nullptr;
    cudaGetSymbolAddress(&sp, g_scratch);
    float* S = (float*)sp;
    float* g_h     = S + OFF_H;
    float* g_x     = S + OFF_X;
    float* g_q     = S + OFF_Q;
    float* g_K     = S + OFF_K;
    float* g_V     = S + OFF_V;
    float* g_sc    = S + OFF_SC;
    float* g_att   = S + OFF_ATT;
    float* g_ff1   = S + OFF_FF1;
    float* g_part  = S + OFF_PART;
    float* g_part2 = S + OFF_PART2;

    cudaMemcpyAsync(g_h, emb, (long)TTOK * DMODEL * sizeof(float),
                    cudaMemcpyDeviceToDevice);
    rms_kernel<<<TTOK, 256>>>(g_h, pre_attn_w, g_x, DMODEL);

    for (int i = 0; i < LAY; i++) {
        bool is_local = ((i + 1) % 6 == 0);
        const float* cosP = is_local ? pe_cos_loc : pe_cos;
        const float* sinP = is_local ? pe_sin_loc : pe_sin;
        const float* mask = is_local ? mask_l : mask_g;

        // qkv = x @ w_qkv[i] : split 6 -> partials consumed by qk_rope
        gemm_mma<false><<<dim3(QKVW / 128, 6, 1), 256>>>(
            g_x, w_qkv + (long)i * DMODEL * QKVW, g_part,
            DMODEL, DMODEL, QKVW, 0, 12, 0, 0, 0);

        cudaMemcpyAsync(g_K, kv_k + (long)i * CCTX * HDIM,
                        (long)CCTX * HDIM * sizeof(float), cudaMemcpyDeviceToDevice);
        copy_v_kernel<<<(HDIM * CCTX + 255) / 256, 256>>>(
            kv_v + (long)i * HDIM * CCTX, g_V);

        qk_rope_kernel<<<TTOK, 256>>>(
            g_part, q_norm_w + (long)i * HDIM, k_norm_w + (long)i * HDIM,
            cosP, sinP, g_q, g_K, g_V,
            kout + (long)i * TTOK * HDIM, vout + (long)i * HDIM * TTOK);

        // scores[h] = q[h] @ K^T : K=256, batch 4
        gemm_mma<true><<<dim3(STOT / 128, 1, NHEAD), 256>>>(
            g_q, g_K, g_sc,
            HDIM, HDIM, HDIM, STOT, 16,
            (long)TTOK * HDIM, 0, (long)TTOK * STOT);

        softmax_kernel<<<dim3(TTOK, NHEAD), 256>>>(g_sc, mask);

        // att[h] = attn[h] @ V^T : K=2048, batch 4, split 8
        gemm_mma<true><<<dim3(HDIM / 128, 8, NHEAD), 256>>>(
            g_sc, g_V, g_part,
            STOT, STOT, STOT, 0, 16,
            (long)TTOK * STOT, 0, 0);
        reduce_split<<<dim3(TTOK * HDIM / 1024, NHEAD), 256>>>(
            g_part, g_att, 8, HDIM, NHEAD * HDIM);

        // proj = att @ w_out[i] : split 8 -> partials summed in add_rms_rms
        gemm_mma<false><<<dim3(DMODEL / 128, 8, 1), 256>>>(
            g_att, w_out + (long)i * (NHEAD * HDIM) * DMODEL, g_part,
            NHEAD * HDIM, NHEAD * HDIM, DMODEL, 0, 8, 0, 0, 0);

        // h += rms(sum(part), post_attn_w); x = rms(h, pre_ff_w)
        add_rms_rms<<<TTOK, 256>>>(
            g_h, g_part, 8,
            post_attn_w + (long)i * DMODEL, pre_ff_w + (long)i * DMODEL, g_x);

        // gate -> part ; up -> part2 ; fused reduce: ff1 = gelu(gate)*up
        gemm_mma<false><<<dim3(FFDIM / 128, 2, 1), 256>>>(
            g_x, w_gate + (long)i * DMODEL * FFDIM, g_part,
            DMODEL, DMODEL, FFDIM, 0, 36, 0, 0, 0);
        gemm_mma<false><<<dim3(FFDIM / 128, 2, 1), 256>>>(
            g_x, w_up + (long)i * DMODEL * FFDIM, g_part2,
            DMODEL, DMODEL, FFDIM, 0, 36, 0, 0, 0);
        reduce_gelu_mul<<<dim3(TTOK * FFDIM / 1024, 1), 256>>>(
            g_part, g_part2, g_ff1, 2);

        // down : split 8 -> partials summed in add_rms_rms
        gemm_mma<false><<<dim3(DMODEL / 128, 8, 1), 256>>>(
            g_ff1, w_down + (long)i * FFDIM * DMODEL, g_part,
            FFDIM, FFDIM, DMODEL, 0, 54, 0, 0, 0);

        const float* next_w = (i + 1 < LAY) ? (pre_attn_w + (long)(i + 1) * DMODEL)
                                            : final_w;
        add_rms_rms<<<TTOK, 256>>>(
            g_h, g_part, 8,
            post_ff_w + (long)i * DMODEL, next_w, g_x);
    }

    // logits = x @ w_lm  (x already = rms(h, final_norm_w))
    gemm_mma<false><<<dim3(VOCAB / 128, 1, 1), 256>>>(
        g_x, w_lm, logits,
        DMODEL, DMODEL, VOCAB, VOCAB, 72, 0, 0, 0);
}

// round 13
// speedup vs baseline: 2.3896x; 1.2221x over previous
#include <cuda_runtime.h>
#include <cuda_bf16.h>
#include <math.h>
#include <stdint.h>

// ---------------------------------------------------------------------------
// Gemma3 prefill forward — Round 12: R7 bf16 hi/lo 3-combo mma.sync GEMM,
// now k32-chunked + double-buffered smem (1 barrier per k32, STS/LDG
// overlapped with MMA).  tcgen05 is unavailable (harness emits compute_103
// virtual PTX, which gates all sm_103a-only features).
// ---------------------------------------------------------------------------

#define LAY    12
#define DMODEL 1152
#define NHEAD  4
#define HDIM   256
#define FFDIM  6912
#define VOCAB  32768
#define TTOK   128
#define CCTX   1920
#define STOT   2048
#define QKVW   1536   // (NH+2)*HD

// ---- scratch (single device global, no allocations) ----
#define OFF_H     0
#define OFF_X     (OFF_H + TTOK*DMODEL)
#define OFF_Q     (OFF_X + TTOK*DMODEL)
#define OFF_K     (OFF_Q + NHEAD*TTOK*HDIM)
#define OFF_V     (OFF_K + STOT*HDIM)
#define OFF_SC    (OFF_V + HDIM*STOT)
#define OFF_ATT   (OFF_SC + NHEAD*TTOK*STOT)
#define OFF_FF1   (OFF_ATT + TTOK*NHEAD*HDIM)
#define OFF_PART  (OFF_FF1 + TTOK*FFDIM)
#define PART_SZ   (16*TTOK*DMODEL)
#define OFF_PART2 (OFF_PART + PART_SZ)
#define SCRATCH_TOTAL (OFF_PART2 + 2*TTOK*FFDIM)

__device__ float g_scratch[SCRATCH_TOTAL];

// ---------------------------------------------------------------------------
// helpers
// ---------------------------------------------------------------------------
__device__ __forceinline__ void mma16816(float* c, const uint32_t* a,
                                         uint32_t b0, uint32_t b1) {
    asm volatile(
        "mma.sync.aligned.m16n8k16.row.col.f32.bf16.bf16.f32 "
        "{%0,%1,%2,%3}, {%4,%5,%6,%7}, {%8,%9}, {%0,%1,%2,%3};"
        : "+f"(c[0]), "+f"(c[1]), "+f"(c[2]), "+f"(c[3])
        : "r"(a[0]), "r"(a[1]), "r"(a[2]), "r"(a[3]), "r"(b0), "r"(b1));
}

__device__ __forceinline__ void ldm4(uint32_t* r, const void* p) {
    uint32_t a = (uint32_t)__cvta_generic_to_shared(p);
    asm volatile("ldmatrix.sync.aligned.m8n8.x4.shared.b16 {%0,%1,%2,%3}, [%4];"
                 : "=r"(r[0]), "=r"(r[1]), "=r"(r[2]), "=r"(r[3]) : "r"(a));
}

// hi = truncated-bf16 pair (PRMT); lo = bf16(x - hi) pair (exact residuals)
__device__ __forceinline__ void cvt_pair(float x0, float x1,
                                         uint32_t& hi2, uint32_t& lo2) {
    uint32_t u0 = __float_as_uint(x0), u1 = __float_as_uint(x1);
    hi2 = __byte_perm(u0, u1, 0x7632);
    float h0 = __uint_as_float(u0 & 0xFFFF0000u);
    float h1 = __uint_as_float(u1 & 0xFFFF0000u);
    float l0 = x0 - h0, l1 = x1 - h1;
    asm("cvt.rn.bf16x2.f32 %0, %1, %2;" : "=r"(lo2) : "f"(l1), "f"(l0));
}

__device__ __forceinline__ void cvt16(const float* f, uint32_t* hi, uint32_t* lo) {
#pragma unroll
    for (int p = 0; p < 8; p++) cvt_pair(f[2*p], f[2*p+1], hi[p], lo[p]);
}

__device__ __forceinline__ float tanh_f(float x) {
    return 1.f - 2.f / (__expf(2.f * x) + 1.f);
}

// ---------------------------------------------------------------------------
// GEMM: C[128, N] = A[128,K] @ B  (BT=0: B KxN row-major; BT=1: B NxK, A@B^T)
// CTA 128x128, 256 threads (8 warps, warp tile 32x64).
// K processed in 32-wide chunks; double-buffered smem stages, ONE
// __syncthreads per chunk; cvt/STS of next chunk + LDG of chunk+2 overlap
// with the 96-MMA/warp block of the current chunk.
// smem plane: 128 rows x 80 bytes (32 bf16 + 8 pad), 4 planes/stage, 2 stages.
// grid = (N/128, split, batch); split>1 -> dense partials [batch][z][128][Nt].
// ---------------------------------------------------------------------------
#define ROWB   80
#define PLANE  (128*ROWB)
#define STG_STRIDE (4*PLANE)
#define P_AHI  0
#define P_ALO  PLANE
#define P_BHI  (2*PLANE)
#define P_BLO  (3*PLANE)
#define GSM_TOTAL (2*STG_STRIDE)   // 81920 bytes

template<bool BT>
__device__ __forceinline__ void load_regs(
    const float* Ab, const float* Bb, int lda, int ldb, int bn, int k0,
    int tid, float* af, float* bf)
{
    const int row = tid >> 1, ks = (tid & 1) * 16;
    const float* ap = Ab + (long)row * lda + k0 + ks;
#pragma unroll
    for (int q = 0; q < 4; q++)
        *(float4*)&af[q * 4] = *(const float4*)(ap + q * 4);
    if (BT) {
        const float* bp = Bb + (long)(bn + row) * ldb + k0 + ks;
#pragma unroll
        for (int q = 0; q < 4; q++)
            *(float4*)&bf[q * 4] = *(const float4*)(bp + q * 4);
    } else {
        const int n = tid & 127, kg = (tid >> 7) * 16;
#pragma unroll
        for (int j = 0; j < 16; j++)
            bf[j] = Bb[(long)(k0 + kg + j) * ldb + bn + n];
    }
}

template<bool BT>
__device__ __forceinline__ void cvt_store(
    char* sm, int stage, int tid, const float* af, const float* bf)
{
    char* base = sm + stage * STG_STRIDE;
    uint32_t hi[8], lo[8];
    {
        const int row = tid >> 1;
        const uint32_t byte = (uint32_t)(row * ROWB + (tid & 1) * 32);
        cvt16(af, hi, lo);
        *(uint4*)(base + P_AHI + byte)      = make_uint4(hi[0], hi[1], hi[2], hi[3]);
        *(uint4*)(base + P_AHI + byte + 16) = make_uint4(hi[4], hi[5], hi[6], hi[7]);
        *(uint4*)(base + P_ALO + byte)      = make_uint4(lo[0], lo[1], lo[2], lo[3]);
        *(uint4*)(base + P_ALO + byte + 16) = make_uint4(lo[4], lo[5], lo[6], lo[7]);
    }
    {
        uint32_t byte;
        if (BT) byte = (uint32_t)((tid >> 1) * ROWB + (tid & 1) * 32);
        else    byte = (uint32_t)((tid & 127) * ROWB + (tid >> 7) * 32);
        cvt16(bf, hi, lo);
        *(uint4*)(base + P_BHI + byte)      = make_uint4(hi[0], hi[1], hi[2], hi[3]);
        *(uint4*)(base + P_BHI + byte + 16) = make_uint4(hi[4], hi[5], hi[6], hi[7]);
        *(uint4*)(base + P_BLO + byte)      = make_uint4(lo[0], lo[1], lo[2], lo[3]);
        *(uint4*)(base + P_BLO + byte + 16) = make_uint4(lo[4], lo[5], lo[6], lo[7]);
    }
}

template<bool BT>
__global__ __launch_bounds__(256) void gemm_mma(
    const float* __restrict__ A, const float* __restrict__ B, float* __restrict__ C,
    int K, int lda, int ldb, int ldc, int kchunks_split,
    long sA, long sB, long sC)
{
    extern __shared__ char sm[];

    const int tid = threadIdx.x;
    const int bz = blockIdx.z, z = blockIdx.y;
    const int bn = blockIdx.x * 128;

    const float* Ab = A + (long)bz * sA;
    const float* Bb = B + (long)bz * sB;

    const int kctot = K >> 5;
    const int kb = z * kchunks_split;
    const int nkc = min(kchunks_split, kctot - kb);

    float acc[2][8][4];
#pragma unroll
    for (int i = 0; i < 2; i++)
#pragma unroll
        for (int j = 0; j < 8; j++)
#pragma unroll
            for (int l = 0; l < 4; l++) acc[i][j][l] = 0.f;

    const int w = tid >> 5, lane = tid & 31;
    const int wm = (w & 3) * 32, wn = (w >> 2) * 64;
    const int r = lane >> 2, cp = (lane & 3) * 2;
    const int grp = lane >> 3, rr = lane & 7;

    float af[16], bf[16];
    load_regs<BT>(Ab, Bb, lda, ldb, bn, kb * 32, tid, af, bf);
    cvt_store<BT>(sm, 0, tid, af, bf);
    if (nkc > 1)
        load_regs<BT>(Ab, Bb, lda, ldb, bn, (kb + 1) * 32, tid, af, bf);
    __syncthreads();

    for (int kc = 0; kc < nkc; kc++) {
        const int sc = kc & 1;

        // fill the other stage with chunk kc+1 (no hazard: it was drained at
        // the sync ending iteration kc-1), then issue LDG for chunk kc+2
        if (kc + 1 < nkc) {
            cvt_store<BT>(sm, sc ^ 1, tid, af, bf);
            if (kc + 2 < nkc)
                load_regs<BT>(Ab, Bb, lda, ldb, bn, (kb + kc + 2) * 32, tid, af, bf);
        }

        // ---- compute on stage sc: 2 k16 sub-tiles x 48 MMA ----
        char* base = sm + sc * STG_STRIDE;
#pragma unroll
        for (int sub = 0; sub < 2; sub++) {
            const int colA = (sub * 16 + (grp >> 1) * 8) * 2;
            const int colB = (sub * 16 + (grp & 1) * 8) * 2;
            uint32_t afr[2][2][4];
#pragma unroll
            for (int h = 0; h < 2; h++) {
                char* pl = base + (h ? P_ALO : P_AHI);
#pragma unroll
                for (int mf = 0; mf < 2; mf++) {
                    int row = wm + mf * 16 + (grp & 1) * 8 + rr;
                    ldm4(afr[h][mf], pl + row * ROWB + colA);
                }
            }
            uint32_t bfr[2][4][4];
#pragma unroll
            for (int h = 0; h < 2; h++) {
                char* pl = base + (h ? P_BLO : P_BHI);
#pragma unroll
                for (int nfp = 0; nfp < 4; nfp++) {
                    int row = wn + nfp * 16 + (grp >> 1) * 8 + rr;
                    ldm4(bfr[h][nfp], pl + row * ROWB + colB);
                }
            }
            // combos: hi*hi, lo*hi, hi*lo
#pragma unroll
            for (int c = 0; c < 3; c++) {
                const int ha = (c == 1) ? 1 : 0;
                const int hb = (c == 2) ? 1 : 0;
#pragma unroll
                for (int nfp = 0; nfp < 4; nfp++)
#pragma unroll
                    for (int s2 = 0; s2 < 2; s2++) {
                        int nf = nfp * 2 + s2;
                        uint32_t b0 = bfr[hb][nfp][s2 * 2];
                        uint32_t b1 = bfr[hb][nfp][s2 * 2 + 1];
                        mma16816(acc[0][nf], afr[ha][0], b0, b1);
                        mma16816(acc[1][nf], afr[ha][1], b0, b1);
                    }
            }
        }
        __syncthreads();
    }

    // ---- writeback ----
    const int Nt = gridDim.x * 128;
    const bool direct = (gridDim.y == 1);
#pragma unroll
    for (int mf = 0; mf < 2; mf++)
#pragma unroll
        for (int nf = 0; nf < 8; nf++) {
            int row = wm + mf * 16 + r;
            int col = bn + wn + nf * 8 + cp;
            float* c = acc[mf][nf];
            if (direct) {
                float* p = C + (long)bz * sC + (long)row * ldc + col;
                *(float2*)p = make_float2(c[0], c[1]);
                *(float2*)(p + 8LL * ldc) = make_float2(c[2], c[3]);
            } else {
                float* p = C + ((long)(bz * gridDim.y + z) * 128 + row) * Nt + col;
                *(float2*)p = make_float2(c[0], c[1]);
                *(float2*)(p + 8LL * Nt) = make_float2(c[2], c[3]);
            }
        }
}

// ---------------------------------------------------------------------------
// Sum split-K partials
// ---------------------------------------------------------------------------
__global__ __launch_bounds__(256) void reduce_split(
    const float* __restrict__ P, float* __restrict__ C,
    int split, int Npart, int ldc)
{
    int bz = blockIdx.y;
    long idx = ((long)blockIdx.x * 256 + threadIdx.x) * 4;
    int m = (int)(idx / Npart);
    int n = (int)(idx % Npart);
    const float* base = P + (long)bz * split * TTOK * Npart + (long)m * Npart + n;
    float4 s = *(const float4*)base;
    for (int t = 1; t < split; t++) {
        float4 v = *(const float4*)(base + (long)t * TTOK * Npart);
        s.x += v.x; s.y += v.y; s.z += v.z; s.w += v.w;
    }
    *(float4*)(C + (long)m * ldc + bz * Npart + n) = s;
}

__device__ __forceinline__ float gelu_t(float x) {
    float x3 = x * x * x;
    return 0.5f * x * (1.f + tanh_f(0.7978845608028654f * (x + 0.044715f * x3)));
}

__global__ __launch_bounds__(256) void reduce_gelu_mul(
    const float* __restrict__ Pa, const float* __restrict__ Pb,
    float* __restrict__ C, int split)
{
    long idx = ((long)blockIdx.x * 256 + threadIdx.x) * 4;
    float4 a = *(const float4*)(Pa + idx);
    float4 b = *(const float4*)(Pb + idx);
    for (int t = 1; t < split; t++) {
        float4 va = *(const float4*)(Pa + idx + (long)t * TTOK * FFDIM);
        float4 vb = *(const float4*)(Pb + idx + (long)t * TTOK * FFDIM);
        a.x += va.x; a.y += va.y; a.z += va.z; a.w += va.w;
        b.x += vb.x; b.y += vb.y; b.z += vb.z; b.w += vb.w;
    }
    float4 o;
    o.x = gelu_t(a.x) * b.x; o.y = gelu_t(a.y) * b.y;
    o.z = gelu_t(a.z) * b.z; o.w = gelu_t(a.w) * b.w;
    *(float4*)(C + idx) = o;
}

// ---------------------------------------------------------------------------
// RMSNorm kernels
// ---------------------------------------------------------------------------
__global__ __launch_bounds__(256) void rms_kernel(
    const float* __restrict__ x, const float* __restrict__ w,
    float* __restrict__ y, int ncols)
{
    int row = blockIdx.x;
    const float* xr = x + (long)row * ncols;
    __shared__ float red[256];
    int tid = threadIdx.x;
    float ss = 0.f;
    for (int c = tid; c < ncols; c += 256) { float v = xr[c]; ss += v * v; }
    red[tid] = ss; __syncthreads();
    for (int s = 128; s > 0; s >>= 1) { if (tid < s) red[tid] += red[tid + s]; __syncthreads(); }
    float inv = rsqrtf(red[0] / ncols + 1e-6f);
    for (int c = tid; c < ncols; c += 256)
        y[(long)row * ncols + c] = xr[c] * inv * (1.f + w[c]);
}

__global__ __launch_bounds__(256) void add_rms_rms(
    float* __restrict__ h, const float* __restrict__ P, int split,
    const float* __restrict__ w1, const float* __restrict__ w2,
    float* __restrict__ x)
{
    int row = blockIdx.x, tid = threadIdx.x;
    __shared__ float red[256];
    float pv[5], hv[5];

    float ssp = 0.f;
#pragma unroll
    for (int j = 0; j < 5; j++) {
        int c = tid + j * 256;
        float v = 0.f;
        if (c < DMODEL) {
            const float* b = P + (long)row * DMODEL + c;
            v = b[0];
            for (int t = 1; t < split; t++) v += b[(long)t * TTOK * DMODEL];
        }
        pv[j] = v; ssp += v * v;
    }
    red[tid] = ssp; __syncthreads();
    for (int s = 128; s > 0; s >>= 1) { if (tid < s) red[tid] += red[tid + s]; __syncthreads(); }
    float inv1 = rsqrtf(red[0] / DMODEL + 1e-6f);
    __syncthreads();

    float ssh = 0.f;
#pragma unroll
    for (int j = 0; j < 5; j++) {
        int c = tid + j * 256;
        float v = 0.f;
        if (c < DMODEL) {
            v = h[(long)row * DMODEL + c] + pv[j] * inv1 * (1.f + w1[c]);
            h[(long)row * DMODEL + c] = v;
        }
        hv[j] = v; ssh += v * v;
    }
    red[tid] = ssh; __syncthreads();
    for (int s = 128; s > 0; s >>= 1) { if (tid < s) red[tid] += red[tid + s]; __syncthreads(); }
    float inv2 = rsqrtf(red[0] / DMODEL + 1e-6f);

#pragma unroll
    for (int j = 0; j < 5; j++) {
        int c = tid + j * 256;
        if (c < DMODEL)
            x[(long)row * DMODEL + c] = hv[j] * inv2 * (1.f + w2[c]);
    }
}

// ---------------------------------------------------------------------------
// Q/K rmsnorm + RoPE + V scatter; qkv read as sum of 6 split-K partials
// ---------------------------------------------------------------------------
__global__ __launch_bounds__(256) void qk_rope_kernel(
    const float* __restrict__ P,
    const float* __restrict__ qw, const float* __restrict__ kw,
    const float* __restrict__ cosp, const float* __restrict__ sinp,
    float* __restrict__ qout, float* __restrict__ Kfull, float* __restrict__ Vfull,
    float* __restrict__ kslice, float* __restrict__ vslice)
{
    int t = blockIdx.x;
    int d = threadIdx.x;
    __shared__ float red[256];
    __shared__ float buf[256];

    float cosv = cosp[t * HDIM + d];
    float sinv = sinp[t * HDIM + d];

    for (int hidx = 0; hidx < 5; hidx++) {
        const float* b = P + (long)t * QKVW + hidx * HDIM + d;
        float v = b[0];
#pragma unroll
        for (int zz = 1; zz < 6; zz++) v += b[(long)zz * TTOK * QKVW];
        red[d] = v * v; __syncthreads();
        for (int s = 128; s > 0; s >>= 1) { if (d < s) red[d] += red[d + s]; __syncthreads(); }
        float inv = rsqrtf(red[0] / HDIM + 1e-6f);
        const float* w = (hidx < 4) ? qw : kw;
        float xn = v * inv * (1.f + w[d]);
        buf[d] = xn; __syncthreads();
        float rot = (d < 128) ? -buf[d + 128] : buf[d - 128];
        float r = xn * cosv + rot * sinv;
        if (hidx < 4) {
            qout[(long)hidx * TTOK * HDIM + (long)t * HDIM + d] = r;
        } else {
            Kfull[(long)(CCTX + t) * HDIM + d] = r;
            kslice[(long)t * HDIM + d] = r;
        }
        __syncthreads();
    }
    const float* b = P + (long)t * QKVW + 5 * HDIM + d;
    float vv = b[0];
#pragma unroll
    for (int zz = 1; zz < 6; zz++) vv += b[(long)zz * TTOK * QKVW];
    Vfull[(long)d * STOT + CCTX + t] = vv;
    vslice[(long)d * TTOK + t] = vv;
}

__global__ __launch_bounds__(256) void copy_v_kernel(
    const float* __restrict__ src, float* __restrict__ Vfull)
{
    int idx = blockIdx.x * 256 + threadIdx.x;
    if (idx < HDIM * CCTX) {
        int d = idx / CCTX, s = idx % CCTX;
        Vfull[(long)d * STOT + s] = src[idx];
    }
}

// ---------------------------------------------------------------------------
// softmax with tanh soft-cap + mask
// ---------------------------------------------------------------------------
__global__ __launch_bounds__(256) void softmax_kernel(
    float* __restrict__ sc, const float* __restrict__ mask)
{
    int t = blockIdx.x, h = blockIdx.y;
    float* row = sc + ((long)h * TTOK + t) * STOT;
    const float* mrow = mask + (long)t * STOT;
    __shared__ float red[256];
    int tid = threadIdx.x;
    const float scale = 0.0625f;
    const float invcap = 1.f / 50.f;

    float vals[8];
    float vmax = -1e30f;
#pragma unroll
    for (int j = 0; j < 8; j++) {
        int s = tid + j * 256;
        float v = row[s] * scale;
        v = tanh_f(v * invcap) * 50.f + mrow[s];
        vals[j] = v;
        vmax = fmaxf(vmax, v);
    }
    red[tid] = vmax; __syncthreads();
    for (int s = 128; s > 0; s >>= 1) { if (tid < s) red[tid] = fmaxf(red[tid], red[tid + s]); __syncthreads(); }
    float m = red[0]; __syncthreads();
    float lsum = 0.f;
#pragma unroll
    for (int j = 0; j < 8; j++) { vals[j] = __expf(vals[j] - m); lsum += vals[j]; }
    red[tid] = lsum; __syncthreads();
    for (int s = 128; s > 0; s >>= 1) { if (tid < s) red[tid] += red[tid + s]; __syncthreads(); }
    float inv = 1.f / red[0];
#pragma unroll
    for (int j = 0; j < 8; j++) row[tid + j * 256] = vals[j] * inv;
}

// ---------------------------------------------------------------------------
// launch
// ---------------------------------------------------------------------------
extern "C" void kernel_launch(void* const* d_in, const int* in_sizes, int n_in,
                              void* d_out, int out_size)
{
    (void)in_sizes; (void)n_in; (void)out_size;
    const float* emb        = (const float*)d_in[0];
    const float* mask_g     = (const float*)d_in[1];
    const float* mask_l     = (const float*)d_in[2];
    const float* pe_cos     = (const float*)d_in[3];
    const float* pe_sin     = (const float*)d_in[4];
    const float* pe_cos_loc = (const float*)d_in[5];
    const float* pe_sin_loc = (const float*)d_in[6];
    const float* kv_k       = (const float*)d_in[7];
    const float* kv_v       = (const float*)d_in[8];
    const float* pre_attn_w = (const float*)d_in[9];
    const float* q_norm_w   = (const float*)d_in[10];
    const float* k_norm_w   = (const float*)d_in[11];
    const float* post_attn_w= (const float*)d_in[12];
    const float* pre_ff_w   = (const float*)d_in[13];
    const float* post_ff_w  = (const float*)d_in[14];
    const float* final_w    = (const float*)d_in[15];
    const float* w_qkv      = (const float*)d_in[16];
    const float* w_out      = (const float*)d_in[17];
    const float* w_gate     = (const float*)d_in[18];
    const float* w_up       = (const float*)d_in[19];
    const float* w_down     = (const float*)d_in[20];
    const float* w_lm       = (const float*)d_in[21];

    float* out    = (float*)d_out;
    float* logits = out;
    float* kout   = out + (long)TTOK * VOCAB;
    float* vout   = kout + (long)LAY * TTOK * HDIM;

    void* sp = nullptr;
    cudaGetSymbolAddress(&sp, g_scratch);
    float* S = (float*)sp;
    float* g_h     = S + OFF_H;
    float* g_x     = S + OFF_X;
    float* g_q     = S + OFF_Q;
    float* g_K     = S + OFF_K;
    float* g_V     = S + OFF_V;
    float* g_sc    = S + OFF_SC;
    float* g_att   = S + OFF_ATT;
    float* g_ff1   = S + OFF_FF1;
    float* g_part  = S + OFF_PART;
    float* g_part2 = S + OFF_PART2;

    cudaFuncSetAttribute(gemm_mma<false>,
                         cudaFuncAttributeMaxDynamicSharedMemorySize, GSM_TOTAL);
    cudaFuncSetAttribute(gemm_mma<true>,
                         cudaFuncAttributeMaxDynamicSharedMemorySize, GSM_TOTAL);

    cudaMemcpyAsync(g_h, emb, (long)TTOK * DMODEL * sizeof(float),
                    cudaMemcpyDeviceToDevice);
    rms_kernel<<<TTOK, 256>>>(g_h, pre_attn_w, g_x, DMODEL);

    for (int i = 0; i < LAY; i++) {
        bool is_local = ((i + 1) % 6 == 0);
        const float* cosP = is_local ? pe_cos_loc : pe_cos;
        const float* sinP = is_local ? pe_sin_loc : pe_sin;
        const float* mask = is_local ? mask_l : mask_g;

        // qkv = x @ w_qkv[i] : K=1152 (36 k32), split 6
        gemm_mma<false><<<dim3(QKVW / 128, 6, 1), 256, GSM_TOTAL>>>(
            g_x, w_qkv + (long)i * DMODEL * QKVW, g_part,
            DMODEL, DMODEL, QKVW, 0, 6, 0, 0, 0);

        cudaMemcpyAsync(g_K, kv_k + (long)i * CCTX * HDIM,
                        (long)CCTX * HDIM * sizeof(float), cudaMemcpyDeviceToDevice);
        copy_v_kernel<<<(HDIM * CCTX + 255) / 256, 256>>>(
            kv_v + (long)i * HDIM * CCTX, g_V);

        qk_rope_kernel<<<TTOK, 256>>>(
            g_part, q_norm_w + (long)i * HDIM, k_norm_w + (long)i * HDIM,
            cosP, sinP, g_q, g_K, g_V,
            kout + (long)i * TTOK * HDIM, vout + (long)i * HDIM * TTOK);

        // scores[h] = q[h] @ K^T : K=256 (8 k32), batch 4
        gemm_mma<true><<<dim3(STOT / 128, 1, NHEAD), 256, GSM_TOTAL>>>(
            g_q, g_K, g_sc,
            HDIM, HDIM, HDIM, STOT, 8,
            (long)TTOK * HDIM, 0, (long)TTOK * STOT);

        softmax_kernel<<<dim3(TTOK, NHEAD), 256>>>(g_sc, mask);

        // att[h] = attn[h] @ V^T : K=2048 (64 k32), batch 4, split 8
        gemm_mma<true><<<dim3(HDIM / 128, 8, NHEAD), 256, GSM_TOTAL>>>(
            g_sc, g_V, g_part,
            STOT, STOT, STOT, 0, 8,
            (long)TTOK * STOT, 0, 0);
        reduce_split<<<dim3(TTOK * HDIM / 1024, NHEAD), 256>>>(
            g_part, g_att, 8, HDIM, NHEAD * HDIM);

        // proj = att @ w_out[i] : K=1024 (32 k32), split 8
        gemm_mma<false><<<dim3(DMODEL / 128, 8, 1), 256, GSM_TOTAL>>>(
            g_att, w_out + (long)i * (NHEAD * HDIM) * DMODEL, g_part,
            NHEAD * HDIM, NHEAD * HDIM, DMODEL, 0, 4, 0, 0, 0);

        add_rms_rms<<<TTOK, 256>>>(
            g_h, g_part, 8,
            post_attn_w + (long)i * DMODEL, pre_ff_w + (long)i * DMODEL, g_x);

        // gate / up : K=1152 (36 k32), split 2
        gemm_mma<false><<<dim3(FFDIM / 128, 2, 1), 256, GSM_TOTAL>>>(
            g_x, w_gate + (long)i * DMODEL * FFDIM, g_part,
            DMODEL, DMODEL, FFDIM, 0, 18, 0, 0, 0);
        gemm_mma<false><<<dim3(FFDIM / 128, 2, 1), 256, GSM_TOTAL>>>(
            g_x, w_up + (long)i * DMODEL * FFDIM, g_part2,
            DMODEL, DMODEL, FFDIM, 0, 18, 0, 0, 0);
        reduce_gelu_mul<<<dim3(TTOK * FFDIM / 1024, 1), 256>>>(
            g_part, g_part2, g_ff1, 2);

        // down : K=6912 (216 k32), split 12 (108 CTAs)
        gemm_mma<false><<<dim3(DMODEL / 128, 12, 1), 256, GSM_TOTAL>>>(
            g_ff1, w_down + (long)i * FFDIM * DMODEL, g_part,
            FFDIM, FFDIM, DMODEL, 0, 18, 0, 0, 0);

        const float* next_w = (i + 1 < LAY) ? (pre_attn_w + (long)(i + 1) * DMODEL)
                                            : final_w;
        add_rms_rms<<<TTOK, 256>>>(
            g_h, g_part, 12,
            post_ff_w + (long)i * DMODEL, next_w, g_x);
    }

    // logits = x @ w_lm : K=1152 (36 k32), 256 CTAs, no split
    gemm_mma<false><<<dim3(VOCAB / 128, 1, 1), 256, GSM_TOTAL>>>(
        g_x, w_lm, logits,
        DMODEL, DMODEL, VOCAB, VOCAB, 36, 0, 0, 0);
}

// round 15
// speedup vs baseline: 2.4631x; 1.0308x over previous
#include <cuda_runtime.h>
#include <cuda_bf16.h>
#include <math.h>
#include <stdint.h>

// ---------------------------------------------------------------------------
// Gemma3 prefill forward — Round 13: R12 pipelined bf16 hi/lo GEMM unchanged;
// node-count attack: gate+up merged into one launch (batch dim w/ pointer-
// difference stride), K/V copies + rope fused into one parallel kv_prep
// kernel.  183 -> ~147 graph nodes.
// ---------------------------------------------------------------------------

#define LAY    12
#define DMODEL 1152
#define NHEAD  4
#define HDIM   256
#define FFDIM  6912
#define VOCAB  32768
#define TTOK   128
#define CCTX   1920
#define STOT   2048
#define QKVW   1536   // (NH+2)*HD

// ---- scratch (single device global, no allocations) ----
#define OFF_H     0
#define OFF_X     (OFF_H + TTOK*DMODEL)
#define OFF_Q     (OFF_X + TTOK*DMODEL)
#define OFF_K     (OFF_Q + NHEAD*TTOK*HDIM)
#define OFF_V     (OFF_K + STOT*HDIM)
#define OFF_SC    (OFF_V + HDIM*STOT)
#define OFF_ATT   (OFF_SC + NHEAD*TTOK*STOT)
#define OFF_FF1   (OFF_ATT + TTOK*NHEAD*HDIM)
#define OFF_PART  (OFF_FF1 + TTOK*FFDIM)
#define PART_SZ   (4*TTOK*FFDIM)     // gate+up: 4 partial sets of [128][6912]
#define SCRATCH_TOTAL (OFF_PART + PART_SZ)

__device__ float g_scratch[SCRATCH_TOTAL];

// ---------------------------------------------------------------------------
// helpers
// ---------------------------------------------------------------------------
__device__ __forceinline__ void mma16816(float* c, const uint32_t* a,
                                         uint32_t b0, uint32_t b1) {
    asm volatile(
        "mma.sync.aligned.m16n8k16.row.col.f32.bf16.bf16.f32 "
        "{%0,%1,%2,%3}, {%4,%5,%6,%7}, {%8,%9}, {%0,%1,%2,%3};"
        : "+f"(c[0]), "+f"(c[1]), "+f"(c[2]), "+f"(c[3])
        : "r"(a[0]), "r"(a[1]), "r"(a[2]), "r"(a[3]), "r"(b0), "r"(b1));
}

__device__ __forceinline__ void ldm4(uint32_t* r, const void* p) {
    uint32_t a = (uint32_t)__cvta_generic_to_shared(p);
    asm volatile("ldmatrix.sync.aligned.m8n8.x4.shared.b16 {%0,%1,%2,%3}, [%4];"
                 : "=r"(r[0]), "=r"(r[1]), "=r"(r[2]), "=r"(r[3]) : "r"(a));
}

// hi = truncated-bf16 pair (PRMT); lo = bf16(x - hi) pair (exact residuals)
__device__ __forceinline__ void cvt_pair(float x0, float x1,
                                         uint32_t& hi2, uint32_t& lo2) {
    uint32_t u0 = __float_as_uint(x0), u1 = __float_as_uint(x1);
    hi2 = __byte_perm(u0, u1, 0x7632);
    float h0 = __uint_as_float(u0 & 0xFFFF0000u);
    float h1 = __uint_as_float(u1 & 0xFFFF0000u);
    float l0 = x0 - h0, l1 = x1 - h1;
    asm("cvt.rn.bf16x2.f32 %0, %1, %2;" : "=r"(lo2) : "f"(l1), "f"(l0));
}

__device__ __forceinline__ void cvt16(const float* f, uint32_t* hi, uint32_t* lo) {
#pragma unroll
    for (int p = 0; p < 8; p++) cvt_pair(f[2*p], f[2*p+1], hi[p], lo[p]);
}

__device__ __forceinline__ float tanh_f(float x) {
    return 1.f - 2.f / (__expf(2.f * x) + 1.f);
}

// ---------------------------------------------------------------------------
// GEMM (unchanged from R12): CTA 128x128, 256 threads, k32 chunks,
// double-buffered smem, 1 sync/chunk.
// ---------------------------------------------------------------------------
#define ROWB   80
#define PLANE  (128*ROWB)
#define STG_STRIDE (4*PLANE)
#define P_AHI  0
#define P_ALO  PLANE
#define P_BHI  (2*PLANE)
#define P_BLO  (3*PLANE)
#define GSM_TOTAL (2*STG_STRIDE)   // 81920 bytes

template<bool BT>
__device__ __forceinline__ void load_regs(
    const float* Ab, const float* Bb, int lda, int ldb, int bn, int k0,
    int tid, float* af, float* bf)
{
    const int row = tid >> 1, ks = (tid & 1) * 16;
    const float* ap = Ab + (long)row * lda + k0 + ks;
#pragma unroll
    for (int q = 0; q < 4; q++)
        *(float4*)&af[q * 4] = *(const float4*)(ap + q * 4);
    if (BT) {
        const float* bp = Bb + (long)(bn + row) * ldb + k0 + ks;
#pragma unroll
        for (int q = 0; q < 4; q++)
            *(float4*)&bf[q * 4] = *(const float4*)(bp + q * 4);
    } else {
        const int n = tid & 127, kg = (tid >> 7) * 16;
#pragma unroll
        for (int j = 0; j < 16; j++)
            bf[j] = Bb[(long)(k0 + kg + j) * ldb + bn + n];
    }
}

template<bool BT>
__device__ __forceinline__ void cvt_store(
    char* sm, int stage, int tid, const float* af, const float* bf)
{
    char* base = sm + stage * STG_STRIDE;
    uint32_t hi[8], lo[8];
    {
        const int row = tid >> 1;
        const uint32_t byte = (uint32_t)(row * ROWB + (tid & 1) * 32);
        cvt16(af, hi, lo);
        *(uint4*)(base + P_AHI + byte)      = make_uint4(hi[0], hi[1], hi[2], hi[3]);
        *(uint4*)(base + P_AHI + byte + 16) = make_uint4(hi[4], hi[5], hi[6], hi[7]);
        *(uint4*)(base + P_ALO + byte)      = make_uint4(lo[0], lo[1], lo[2], lo[3]);
        *(uint4*)(base + P_ALO + byte + 16) = make_uint4(lo[4], lo[5], lo[6], lo[7]);
    }
    {
        uint32_t byte;
        if (BT) byte = (uint32_t)((tid >> 1) * ROWB + (tid & 1) * 32);
        else    byte = (uint32_t)((tid & 127) * ROWB + (tid >> 7) * 32);
        cvt16(bf, hi, lo);
        *(uint4*)(base + P_BHI + byte)      = make_uint4(hi[0], hi[1], hi[2], hi[3]);
        *(uint4*)(base + P_BHI + byte + 16) = make_uint4(hi[4], hi[5], hi[6], hi[7]);
        *(uint4*)(base + P_BLO + byte)      = make_uint4(lo[0], lo[1], lo[2], lo[3]);
        *(uint4*)(base + P_BLO + byte + 16) = make_uint4(lo[4], lo[5], lo[6], lo[7]);
    }
}

template<bool BT>
__global__ __launch_bounds__(256) void gemm_mma(
    const float* __restrict__ A, const float* __restrict__ B, float* __restrict__ C,
    int K, int lda, int ldb, int ldc, int kchunks_split,
    long sA, long sB, long sC)
{
    extern __shared__ char sm[];

    const int tid = threadIdx.x;
    const int bz = blockIdx.z, z = blockIdx.y;
    const int bn = blockIdx.x * 128;

    const float* Ab = A + (long)bz * sA;
    const float* Bb = B + (long)bz * sB;

    const int kctot = K >> 5;
    const int kb = z * kchunks_split;
    const int nkc = min(kchunks_split, kctot - kb);

    float acc[2][8][4];
#pragma unroll
    for (int i = 0; i < 2; i++)
#pragma unroll
        for (int j = 0; j < 8; j++)
#pragma unroll
            for (int l = 0; l < 4; l++) acc[i][j][l] = 0.f;

    const int w = tid >> 5, lane = tid & 31;
    const int wm = (w & 3) * 32, wn = (w >> 2) * 64;
    const int r = lane >> 2, cp = (lane & 3) * 2;
    const int grp = lane >> 3, rr = lane & 7;

    float af[16], bf[16];
    load_regs<BT>(Ab, Bb, lda, ldb, bn, kb * 32, tid, af, bf);
    cvt_store<BT>(sm, 0, tid, af, bf);
    if (nkc > 1)
        load_regs<BT>(Ab, Bb, lda, ldb, bn, (kb + 1) * 32, tid, af, bf);
    __syncthreads();

    for (int kc = 0; kc < nkc; kc++) {
        const int sc = kc & 1;

        if (kc + 1 < nkc) {
            cvt_store<BT>(sm, sc ^ 1, tid, af, bf);
            if (kc + 2 < nkc)
                load_regs<BT>(Ab, Bb, lda, ldb, bn, (kb + kc + 2) * 32, tid, af, bf);
        }

        char* base = sm + sc * STG_STRIDE;
#pragma unroll
        for (int sub = 0; sub < 2; sub++) {
            const int colA = (sub * 16 + (grp >> 1) * 8) * 2;
            const int colB = (sub * 16 + (grp & 1) * 8) * 2;
            uint32_t afr[2][2][4];
#pragma unroll
            for (int h = 0; h < 2; h++) {
                char* pl = base + (h ? P_ALO : P_AHI);
#pragma unroll
                for (int mf = 0; mf < 2; mf++) {
                    int row = wm + mf * 16 + (grp & 1) * 8 + rr;
                    ldm4(afr[h][mf], pl + row * ROWB + colA);
                }
            }
            uint32_t bfr[2][4][4];
#pragma unroll
            for (int h = 0; h < 2; h++) {
                char* pl = base + (h ? P_BLO : P_BHI);
#pragma unroll
                for (int nfp = 0; nfp < 4; nfp++) {
                    int row = wn + nfp * 16 + (grp >> 1) * 8 + rr;
                    ldm4(bfr[h][nfp], pl + row * ROWB + colB);
                }
            }
#pragma unroll
            for (int c = 0; c < 3; c++) {
                const int ha = (c == 1) ? 1 : 0;
                const int hb = (c == 2) ? 1 : 0;
#pragma unroll
                for (int nfp = 0; nfp < 4; nfp++)
#pragma unroll
                    for (int s2 = 0; s2 < 2; s2++) {
                        int nf = nfp * 2 + s2;
                        uint32_t b0 = bfr[hb][nfp][s2 * 2];
                        uint32_t b1 = bfr[hb][nfp][s2 * 2 + 1];
                        mma16816(acc[0][nf], afr[ha][0], b0, b1);
                        mma16816(acc[1][nf], afr[ha][1], b0, b1);
                    }
            }
        }
        __syncthreads();
    }

    const int Nt = gridDim.x * 128;
    const bool direct = (gridDim.y == 1 && gridDim.z == 1) ||
                        (gridDim.y == 1 && sC != 0);
#pragma unroll
    for (int mf = 0; mf < 2; mf++)
#pragma unroll
        for (int nf = 0; nf < 8; nf++) {
            int row = wm + mf * 16 + r;
            int col = bn + wn + nf * 8 + cp;
            float* c = acc[mf][nf];
            if (direct) {
                float* p = C + (long)bz * sC + (long)row * ldc + col;
                *(float2*)p = make_float2(c[0], c[1]);
                *(float2*)(p + 8LL * ldc) = make_float2(c[2], c[3]);
            } else {
                float* p = C + ((long)(bz * gridDim.y + z) * 128 + row) * Nt + col;
                *(float2*)p = make_float2(c[0], c[1]);
                *(float2*)(p + 8LL * Nt) = make_float2(c[2], c[3]);
            }
        }
}

// ---------------------------------------------------------------------------
// Sum split-K partials
// ---------------------------------------------------------------------------
__global__ __launch_bounds__(256) void reduce_split(
    const float* __restrict__ P, float* __restrict__ C,
    int split, int Npart, int ldc)
{
    int bz = blockIdx.y;
    long idx = ((long)blockIdx.x * 256 + threadIdx.x) * 4;
    int m = (int)(idx / Npart);
    int n = (int)(idx % Npart);
    const float* base = P + (long)bz * split * TTOK * Npart + (long)m * Npart + n;
    float4 s = *(const float4*)base;
    for (int t = 1; t < split; t++) {
        float4 v = *(const float4*)(base + (long)t * TTOK * Npart);
        s.x += v.x; s.y += v.y; s.z += v.z; s.w += v.w;
    }
    *(float4*)(C + (long)m * ldc + bz * Npart + n) = s;
}

__device__ __forceinline__ float gelu_t(float x) {
    float x3 = x * x * x;
    return 0.5f * x * (1.f + tanh_f(0.7978845608028654f * (x + 0.044715f * x3)));
}

__global__ __launch_bounds__(256) void reduce_gelu_mul(
    const float* __restrict__ Pa, const float* __restrict__ Pb,
    float* __restrict__ C, int split)
{
    long idx = ((long)blockIdx.x * 256 + threadIdx.x) * 4;
    float4 a = *(const float4*)(Pa + idx);
    float4 b = *(const float4*)(Pb + idx);
    for (int t = 1; t < split; t++) {
        float4 va = *(const float4*)(Pa + idx + (long)t * TTOK * FFDIM);
        float4 vb = *(const float4*)(Pb + idx + (long)t * TTOK * FFDIM);
        a.x += va.x; a.y += va.y; a.z += va.z; a.w += va.w;
        b.x += vb.x; b.y += vb.y; b.z += vb.z; b.w += vb.w;
    }
    float4 o;
    o.x = gelu_t(a.x) * b.x; o.y = gelu_t(a.y) * b.y;
    o.z = gelu_t(a.z) * b.z; o.w = gelu_t(a.w) * b.w;
    *(float4*)(C + idx) = o;
}

// ---------------------------------------------------------------------------
// RMSNorm kernels
// ---------------------------------------------------------------------------
__global__ __launch_bounds__(256) void rms_kernel(
    const float* __restrict__ x, const float* __restrict__ w,
    float* __restrict__ y, int ncols)
{
    int row = blockIdx.x;
    const float* xr = x + (long)row * ncols;
    __shared__ float red[256];
    int tid = threadIdx.x;
    float ss = 0.f;
    for (int c = tid; c < ncols; c += 256) { float v = xr[c]; ss += v * v; }
    red[tid] = ss; __syncthreads();
    for (int s = 128; s > 0; s >>= 1) { if (tid < s) red[tid] += red[tid + s]; __syncthreads(); }
    float inv = rsqrtf(red[0] / ncols + 1e-6f);
    for (int c = tid; c < ncols; c += 256)
        y[(long)row * ncols + c] = xr[c] * inv * (1.f + w[c]);
}

__global__ __launch_bounds__(256) void add_rms_rms(
    float* __restrict__ h, const float* __restrict__ P, int split,
    const float* __restrict__ w1, const float* __restrict__ w2,
    float* __restrict__ x)
{
    int row = blockIdx.x, tid = threadIdx.x;
    __shared__ float red[256];
    float pv[5], hv[5];

    float ssp = 0.f;
#pragma unroll
    for (int j = 0; j < 5; j++) {
        int c = tid + j * 256;
        float v = 0.f;
        if (c < DMODEL) {
            const float* b = P + (long)row * DMODEL + c;
            v = b[0];
            for (int t = 1; t < split; t++) v += b[(long)t * TTOK * DMODEL];
        }
        pv[j] = v; ssp += v * v;
    }
    red[tid] = ssp; __syncthreads();
    for (int s = 128; s > 0; s >>= 1) { if (tid < s) red[tid] += red[tid + s]; __syncthreads(); }
    float inv1 = rsqrtf(red[0] / DMODEL + 1e-6f);
    __syncthreads();

    float ssh = 0.f;
#pragma unroll
    for (int j = 0; j < 5; j++) {
        int c = tid + j * 256;
        float v = 0.f;
        if (c < DMODEL) {
            v = h[(long)row * DMODEL + c] + pv[j] * inv1 * (1.f + w1[c]);
            h[(long)row * DMODEL + c] = v;
        }
        hv[j] = v; ssh += v * v;
    }
    red[tid] = ssh; __syncthreads();
    for (int s = 128; s > 0; s >>= 1) { if (tid < s) red[tid] += red[tid + s]; __syncthreads(); }
    float inv2 = rsqrtf(red[0] / DMODEL + 1e-6f);

#pragma unroll
    for (int j = 0; j < 5; j++) {
        int c = tid + j * 256;
        if (c < DMODEL)
            x[(long)row * DMODEL + c] = hv[j] * inv2 * (1.f + w2[c]);
    }
}

// ---------------------------------------------------------------------------
// kv_prep: fused (a) per-(token,section) qk rmsnorm+rope / v scatter reading
// 6 qkv split-K partials, (b) K-cache copy, (c) V-cache transpose copy.
// grid.x = 128*6 + 1920 + 1920 = 4608, 256 threads.
// ---------------------------------------------------------------------------
__global__ __launch_bounds__(256) void kv_prep_kernel(
    const float* __restrict__ P,
    const float* __restrict__ qw, const float* __restrict__ kw,
    const float* __restrict__ cosp, const float* __restrict__ sinp,
    const float* __restrict__ ksrc, const float* __restrict__ vsrc,
    float* __restrict__ qout, float* __restrict__ Kfull, float* __restrict__ Vfull,
    float* __restrict__ kslice, float* __restrict__ vslice)
{
    const int bid = blockIdx.x;
    const int tid = threadIdx.x;

    if (bid < 768) {                       // rope / v-scatter: (t, section)
        const int t = bid & 127, s = bid >> 7;
        const int d = tid;
        const float* b = P + (long)t * QKVW + s * HDIM + d;
        float v = b[0];
#pragma unroll
        for (int zz = 1; zz < 6; zz++) v += b[(long)zz * TTOK * QKVW];

        if (s == 5) {                      // v
            Vfull[(long)d * STOT + CCTX + t] = v;
            vslice[(long)d * TTOK + t] = v;
            return;
        }
        __shared__ float red[256];
        __shared__ float buf[256];
        red[d] = v * v; __syncthreads();
        for (int st = 128; st > 0; st >>= 1) {
            if (d < st) red[d] += red[d + st];
            __syncthreads();
        }
        float inv = rsqrtf(red[0] / HDIM + 1e-6f);
        const float* w = (s < 4) ? qw : kw;
        float xn = v * inv * (1.f + w[d]);
        buf[d] = xn; __syncthreads();
        float rot = (d < 128) ? -buf[d + 128] : buf[d - 128];
        float r = xn * cosp[t * HDIM + d] + rot * sinp[t * HDIM + d];
        if (s < 4) {
            qout[(long)s * TTOK * HDIM + (long)t * HDIM + d] = r;
        } else {
            Kfull[(long)(CCTX + t) * HDIM + d] = r;
            kslice[(long)t * HDIM + d] = r;
        }
    } else if (bid < 768 + 1920) {         // K copy: one row of 256 floats
        const int row = bid - 768;
        Kfull[(long)row * HDIM + tid] = ksrc[(long)row * HDIM + tid];
    } else {                               // V copy (transpose layout fix)
        long idx = (long)(bid - 2688) * 256 + tid;
        int d = (int)(idx / CCTX), s2 = (int)(idx % CCTX);
        Vfull[(long)d * STOT + s2] = vsrc[idx];
    }
}

// ---------------------------------------------------------------------------
// softmax with tanh soft-cap + mask
// ---------------------------------------------------------------------------
__global__ __launch_bounds__(256) void softmax_kernel(
    float* __restrict__ sc, const float* __restrict__ mask)
{
    int t = blockIdx.x, h = blockIdx.y;
    float* row = sc + ((long)h * TTOK + t) * STOT;
    const float* mrow = mask + (long)t * STOT;
    __shared__ float red[256];
    int tid = threadIdx.x;
    const float scale = 0.0625f;
    const float invcap = 1.f / 50.f;

    float vals[8];
    float vmax = -1e30f;
#pragma unroll
    for (int j = 0; j < 8; j++) {
        int s = tid + j * 256;
        float v = row[s] * scale;
        v = tanh_f(v * invcap) * 50.f + mrow[s];
        vals[j] = v;
        vmax = fmaxf(vmax, v);
    }
    red[tid] = vmax; __syncthreads();
    for (int s = 128; s > 0; s >>= 1) { if (tid < s) red[tid] = fmaxf(red[tid], red[tid + s]); __syncthreads(); }
    float m = red[0]; __syncthreads();
    float lsum = 0.f;
#pragma unroll
    for (int j = 0; j < 8; j++) { vals[j] = __expf(vals[j] - m); lsum += vals[j]; }
    red[tid] = lsum; __syncthreads();
    for (int s = 128; s > 0; s >>= 1) { if (tid < s) red[tid] += red[tid + s]; __syncthreads(); }
    float inv = 1.f / red[0];
#pragma unroll
    for (int j = 0; j < 8; j++) row[tid + j * 256] = vals[j] * inv;
}

// ---------------------------------------------------------------------------
// launch
// ---------------------------------------------------------------------------
extern "C" void kernel_launch(void* const* d_in, const int* in_sizes, int n_in,
                              void* d_out, int out_size)
{
    (void)in_sizes; (void)n_in; (void)out_size;
    const float* emb        = (const float*)d_in[0];
    const float* mask_g     = (const float*)d_in[1];
    const float* mask_l     = (const float*)d_in[2];
    const float* pe_cos     = (const float*)d_in[3];
    const float* pe_sin     = (const float*)d_in[4];
    const float* pe_cos_loc = (const float*)d_in[5];
    const float* pe_sin_loc = (const float*)d_in[6];
    const float* kv_k       = (const float*)d_in[7];
    const float* kv_v       = (const float*)d_in[8];
    const float* pre_attn_w = (const float*)d_in[9];
    const float* q_norm_w   = (const float*)d_in[10];
    const float* k_norm_w   = (const float*)d_in[11];
    const float* post_attn_w= (const float*)d_in[12];
    const float* pre_ff_w   = (const float*)d_in[13];
    const float* post_ff_w  = (const float*)d_in[14];
    const float* final_w    = (const float*)d_in[15];
    const float* w_qkv      = (const float*)d_in[16];
    const float* w_out      = (const float*)d_in[17];
    const float* w_gate     = (const float*)d_in[18];
    const float* w_up       = (const float*)d_in[19];
    const float* w_down     = (const float*)d_in[20];
    const float* w_lm       = (const float*)d_in[21];

    float* out    = (float*)d_out;
    float* logits = out;
    float* kout   = out + (long)TTOK * VOCAB;
    float* vout   = kout + (long)LAY * TTOK * HDIM;

    void* sp = nullptr;
    cudaGetSymbolAddress(&sp, g_scratch);
    float* S = (float*)sp;
    float* g_h     = S + OFF_H;
    float* g_x     = S + OFF_X;
    float* g_q     = S + OFF_Q;
    float* g_K     = S + OFF_K;
    float* g_V     = S + OFF_V;
    float* g_sc    = S + OFF_SC;
    float* g_att   = S + OFF_ATT;
    float* g_ff1   = S + OFF_FF1;
    float* g_part  = S + OFF_PART;
    float* g_partB = g_part + 2L * TTOK * FFDIM;   // "up" partial sets (2,3)

    cudaFuncSetAttribute(gemm_mma<false>,
                         cudaFuncAttributeMaxDynamicSharedMemorySize, GSM_TOTAL);
    cudaFuncSetAttribute(gemm_mma<true>,
                         cudaFuncAttributeMaxDynamicSharedMemorySize, GSM_TOTAL);

    cudaMemcpyAsync(g_h, emb, (long)TTOK * DMODEL * sizeof(float),
                    cudaMemcpyDeviceToDevice);
    rms_kernel<<<TTOK, 256>>>(g_h, pre_attn_w, g_x, DMODEL);

    for (int i = 0; i < LAY; i++) {
        bool is_local = ((i + 1) % 6 == 0);
        const float* cosP = is_local ? pe_cos_loc : pe_cos;
        const float* sinP = is_local ? pe_sin_loc : pe_sin;
        const float* mask = is_local ? mask_l : mask_g;

        // qkv = x @ w_qkv[i] : K=1152 (36 k32), split 6
        gemm_mma<false><<<dim3(QKVW / 128, 6, 1), 256, GSM_TOTAL>>>(
            g_x, w_qkv + (long)i * DMODEL * QKVW, g_part,
            DMODEL, DMODEL, QKVW, 0, 6, 0, 0, 0);

        // fused: rope (qkv partial-sum) + K copy + V transpose copy
        kv_prep_kernel<<<4608, 256>>>(
            g_part, q_norm_w + (long)i * HDIM, k_norm_w + (long)i * HDIM,
            cosP, sinP,
            kv_k + (long)i * CCTX * HDIM, kv_v + (long)i * HDIM * CCTX,
            g_q, g_K, g_V,
            kout + (long)i * TTOK * HDIM, vout + (long)i * HDIM * TTOK);

        // scores[h] = q[h] @ K^T : K=256 (8 k32), batch 4
        gemm_mma<true><<<dim3(STOT / 128, 1, NHEAD), 256, GSM_TOTAL>>>(
            g_q, g_K, g_sc,
            HDIM, HDIM, HDIM, STOT, 8,
            (long)TTOK * HDIM, 0, (long)TTOK * STOT);

        softmax_kernel<<<dim3(TTOK, NHEAD), 256>>>(g_sc, mask);

        // att[h] = attn[h] @ V^T : K=2048 (64 k32), batch 4, split 8
        gemm_mma<true><<<dim3(HDIM / 128, 8, NHEAD), 256, GSM_TOTAL>>>(
            g_sc, g_V, g_part,
            STOT, STOT, STOT, 0, 8,
            (long)TTOK * STOT, 0, 0);
        reduce_split<<<dim3(TTOK * HDIM / 1024, NHEAD), 256>>>(
            g_part, g_att, 8, HDIM, NHEAD * HDIM);

        // proj = att @ w_out[i] : K=1024 (32 k32), split 8
        gemm_mma<false><<<dim3(DMODEL / 128, 8, 1), 256, GSM_TOTAL>>>(
            g_att, w_out + (long)i * (NHEAD * HDIM) * DMODEL, g_part,
            NHEAD * HDIM, NHEAD * HDIM, DMODEL, 0, 4, 0, 0, 0);

        add_rms_rms<<<TTOK, 256>>>(
            g_h, g_part, 8,
            post_attn_w + (long)i * DMODEL, pre_ff_w + (long)i * DMODEL, g_x);

        // gate (bz=0) + up (bz=1) in ONE launch: batch stride = w_up - w_gate
        gemm_mma<false><<<dim3(FFDIM / 128, 2, 2), 256, GSM_TOTAL>>>(
            g_x, w_gate + (long)i * DMODEL * FFDIM, g_part,
            DMODEL, DMODEL, FFDIM, 0, 18,
            0, (long)(w_up - w_gate), 0);
        reduce_gelu_mul<<<dim3(TTOK * FFDIM / 1024, 1), 256>>>(
            g_part, g_partB, g_ff1, 2);

        // down : K=6912 (216 k32), split 12 (108 CTAs)
        gemm_mma<false><<<dim3(DMODEL / 128, 12, 1), 256, GSM_TOTAL>>>(
            g_ff1, w_down + (long)i * FFDIM * DMODEL, g_part,
            FFDIM, FFDIM, DMODEL, 0, 18, 0, 0, 0);

        const float* next_w = (i + 1 < LAY) ? (pre_attn_w + (long)(i + 1) * DMODEL)
                                            : final_w;
        add_rms_rms<<<TTOK, 256>>>(
            g_h, g_part, 12,
            post_ff_w + (long)i * DMODEL, next_w, g_x);
    }

    // logits = x @ w_lm : K=1152 (36 k32), 256 CTAs, no split
    gemm_mma<false><<<dim3(VOCAB / 128, 1, 1), 256, GSM_TOTAL>>>(
        g_x, w_lm, logits,
        DMODEL, DMODEL, VOCAB, VOCAB, 36, 0, 0, 0);
}

// round 16
// speedup vs baseline: 2.7795x; 1.1284x over previous
#include <cuda_runtime.h>
#include <cuda_bf16.h>
#include <math.h>
#include <stdint.h>

// ---------------------------------------------------------------------------
// Gemma3 prefill forward — Round 15: GEMM retiled to 128x64 CTAs with
// __launch_bounds__(256,2) -> 2 CTAs/SM (was 1), doubling warp-level overlap
// and grid coverage.  Pipeline (k32 chunks, double-buffered smem, bf16 hi/lo
// 3-combo mma.sync) and all aux kernels unchanged from R13.
// ---------------------------------------------------------------------------

#define LAY    12
#define DMODEL 1152
#define NHEAD  4
#define HDIM   256
#define FFDIM  6912
#define VOCAB  32768
#define TTOK   128
#define CCTX   1920
#define STOT   2048
#define QKVW   1536   // (NH+2)*HD

// ---- scratch (single device global, no allocations) ----
#define OFF_H     0
#define OFF_X     (OFF_H + TTOK*DMODEL)
#define OFF_Q     (OFF_X + TTOK*DMODEL)
#define OFF_K     (OFF_Q + NHEAD*TTOK*HDIM)
#define OFF_V     (OFF_K + STOT*HDIM)
#define OFF_SC    (OFF_V + HDIM*STOT)
#define OFF_ATT   (OFF_SC + NHEAD*TTOK*STOT)
#define OFF_FF1   (OFF_ATT + TTOK*NHEAD*HDIM)
#define OFF_PART  (OFF_FF1 + TTOK*FFDIM)
#define PART_SZ   (4*TTOK*FFDIM)     // gate+up: 4 partial sets of [128][6912]
#define SCRATCH_TOTAL (OFF_PART + PART_SZ)

__device__ float g_scratch[SCRATCH_TOTAL];

// ---------------------------------------------------------------------------
// helpers
// ---------------------------------------------------------------------------
__device__ __forceinline__ void mma16816(float* c, const uint32_t* a,
                                         uint32_t b0, uint32_t b1) {
    asm volatile(
        "mma.sync.aligned.m16n8k16.row.col.f32.bf16.bf16.f32 "
        "{%0,%1,%2,%3}, {%4,%5,%6,%7}, {%8,%9}, {%0,%1,%2,%3};"
        : "+f"(c[0]), "+f"(c[1]), "+f"(c[2]), "+f"(c[3])
        : "r"(a[0]), "r"(a[1]), "r"(a[2]), "r"(a[3]), "r"(b0), "r"(b1));
}

__device__ __forceinline__ void ldm4(uint32_t* r, const void* p) {
    uint32_t a = (uint32_t)__cvta_generic_to_shared(p);
    asm volatile("ldmatrix.sync.aligned.m8n8.x4.shared.b16 {%0,%1,%2,%3}, [%4];"
                 : "=r"(r[0]), "=r"(r[1]), "=r"(r[2]), "=r"(r[3]) : "r"(a));
}

// hi = truncated-bf16 pair (PRMT); lo = bf16(x - hi) pair (exact residuals)
__device__ __forceinline__ void cvt_pair(float x0, float x1,
                                         uint32_t& hi2, uint32_t& lo2) {
    uint32_t u0 = __float_as_uint(x0), u1 = __float_as_uint(x1);
    hi2 = __byte_perm(u0, u1, 0x7632);
    float h0 = __uint_as_float(u0 & 0xFFFF0000u);
    float h1 = __uint_as_float(u1 & 0xFFFF0000u);
    float l0 = x0 - h0, l1 = x1 - h1;
    asm("cvt.rn.bf16x2.f32 %0, %1, %2;" : "=r"(lo2) : "f"(l1), "f"(l0));
}

__device__ __forceinline__ void cvt16(const float* f, uint32_t* hi, uint32_t* lo) {
#pragma unroll
    for (int p = 0; p < 8; p++) cvt_pair(f[2*p], f[2*p+1], hi[p], lo[p]);
}

__device__ __forceinline__ void cvt8v(const float* f, uint32_t* hi, uint32_t* lo) {
#pragma unroll
    for (int p = 0; p < 4; p++) cvt_pair(f[2*p], f[2*p+1], hi[p], lo[p]);
}

__device__ __forceinline__ float tanh_f(float x) {
    return 1.f - 2.f / (__expf(2.f * x) + 1.f);
}

// ---------------------------------------------------------------------------
// GEMM: C[128, N] = A[128,K] @ B  (BT=0: B KxN row-major; BT=1: B NxK, A@B^T)
// CTA tile 128x64, 256 threads (8 warps, warp tile 32x32), k32 chunks,
// double-buffered smem, 1 sync/chunk, 2 CTAs/SM.
// smem: A planes 128x80B, B planes 64x80B; stage = 30720 B, total 61440 B.
// grid = (N/64, split, batch); split>1 -> dense partials [batch][z][128][Nt].
// ---------------------------------------------------------------------------
#define ROWB   80
#define APLANE (128*ROWB)
#define BPLANE (64*ROWB)
#define STG_STRIDE (2*APLANE + 2*BPLANE)
#define P_AHI  0
#define P_ALO  APLANE
#define P_BHI  (2*APLANE)
#define P_BLO  (2*APLANE + BPLANE)
#define GSM_TOTAL (2*STG_STRIDE)   // 61440 bytes

template<bool BT>
__device__ __forceinline__ void load_regs(
    const float* Ab, const float* Bb, int lda, int ldb, int bn, int k0,
    int tid, float* af, float* bf)
{
    const int row = tid >> 1, ks = (tid & 1) * 16;
    const float* ap = Ab + (long)row * lda + k0 + ks;
#pragma unroll
    for (int q = 0; q < 4; q++)
        *(float4*)&af[q * 4] = *(const float4*)(ap + q * 4);
    if (BT) {
        const int brow = tid >> 2, bks = (tid & 3) * 8;
        const float* bp = Bb + (long)(bn + brow) * ldb + k0 + bks;
        *(float4*)&bf[0] = *(const float4*)bp;
        *(float4*)&bf[4] = *(const float4*)(bp + 4);
    } else {
        const int n = tid & 63, kg = tid >> 6;   // 4 k-groups of 8
#pragma unroll
        for (int j = 0; j < 8; j++)
            bf[j] = Bb[(long)(k0 + kg * 8 + j) * ldb + bn + n];
    }
}

template<bool BT>
__device__ __forceinline__ void cvt_store(
    char* sm, int stage, int tid, const float* af, const float* bf)
{
    char* base = sm + stage * STG_STRIDE;
    {
        uint32_t hi[8], lo[8];
        const int row = tid >> 1;
        const uint32_t byte = (uint32_t)(row * ROWB + (tid & 1) * 32);
        cvt16(af, hi, lo);
        *(uint4*)(base + P_AHI + byte)      = make_uint4(hi[0], hi[1], hi[2], hi[3]);
        *(uint4*)(base + P_AHI + byte + 16) = make_uint4(hi[4], hi[5], hi[6], hi[7]);
        *(uint4*)(base + P_ALO + byte)      = make_uint4(lo[0], lo[1], lo[2], lo[3]);
        *(uint4*)(base + P_ALO + byte + 16) = make_uint4(lo[4], lo[5], lo[6], lo[7]);
    }
    {
        uint32_t hi[4], lo[4];
        uint32_t byte;
        if (BT) byte = (uint32_t)((tid >> 2) * ROWB + (tid & 3) * 16);
        else    byte = (uint32_t)((tid & 63) * ROWB + (tid >> 6) * 16);
        cvt8v(bf, hi, lo);
        *(uint4*)(base + P_BHI + byte) = make_uint4(hi[0], hi[1], hi[2], hi[3]);
        *(uint4*)(base + P_BLO + byte) = make_uint4(lo[0], lo[1], lo[2], lo[3]);
    }
}

template<bool BT>
__global__ __launch_bounds__(256, 2) void gemm_mma(
    const float* __restrict__ A, const float* __restrict__ B, float* __restrict__ C,
    int K, int lda, int ldb, int ldc, int kchunks_split,
    long sA, long sB, long sC)
{
    extern __shared__ char sm[];

    const int tid = threadIdx.x;
    const int bz = blockIdx.z, z = blockIdx.y;
    const int bn = blockIdx.x * 64;

    const float* Ab = A + (long)bz * sA;
    const float* Bb = B + (long)bz * sB;

    const int kctot = K >> 5;
    const int kb = z * kchunks_split;
    const int nkc = min(kchunks_split, kctot - kb);

    float acc[2][4][4];
#pragma unroll
    for (int i = 0; i < 2; i++)
#pragma unroll
        for (int j = 0; j < 4; j++)
#pragma unroll
            for (int l = 0; l < 4; l++) acc[i][j][l] = 0.f;

    const int w = tid >> 5, lane = tid & 31;
    const int wm = (w & 3) * 32, wn = (w >> 2) * 32;
    const int r = lane >> 2, cp = (lane & 3) * 2;
    const int grp = lane >> 3, rr = lane & 7;

    float af[16], bf[8];
    load_regs<BT>(Ab, Bb, lda, ldb, bn, kb * 32, tid, af, bf);
    cvt_store<BT>(sm, 0, tid, af, bf);
    if (nkc > 1)
        load_regs<BT>(Ab, Bb, lda, ldb, bn, (kb + 1) * 32, tid, af, bf);
    __syncthreads();

    for (int kc = 0; kc < nkc; kc++) {
        const int sc = kc & 1;

        if (kc + 1 < nkc) {
            cvt_store<BT>(sm, sc ^ 1, tid, af, bf);
            if (kc + 2 < nkc)
                load_regs<BT>(Ab, Bb, lda, ldb, bn, (kb + kc + 2) * 32, tid, af, bf);
        }

        char* base = sm + sc * STG_STRIDE;
#pragma unroll
        for (int sub = 0; sub < 2; sub++) {
            const int colA = (sub * 16 + (grp >> 1) * 8) * 2;
            const int colB = (sub * 16 + (grp & 1) * 8) * 2;
            uint32_t afr[2][2][4];
#pragma unroll
            for (int h = 0; h < 2; h++) {
                char* pl = base + (h ? P_ALO : P_AHI);
#pragma unroll
                for (int mf = 0; mf < 2; mf++) {
                    int row = wm + mf * 16 + (grp & 1) * 8 + rr;
                    ldm4(afr[h][mf], pl + row * ROWB + colA);
                }
            }
            uint32_t bfr[2][2][4];
#pragma unroll
            for (int h = 0; h < 2; h++) {
                char* pl = base + (h ? P_BLO : P_BHI);
#pragma unroll
                for (int nfp = 0; nfp < 2; nfp++) {
                    int row = wn + nfp * 16 + (grp >> 1) * 8 + rr;
                    ldm4(bfr[h][nfp], pl + row * ROWB + colB);
                }
            }
#pragma unroll
            for (int c = 0; c < 3; c++) {
                const int ha = (c == 1) ? 1 : 0;
                const int hb = (c == 2) ? 1 : 0;
#pragma unroll
                for (int nfp = 0; nfp < 2; nfp++)
#pragma unroll
                    for (int s2 = 0; s2 < 2; s2++) {
                        int nf = nfp * 2 + s2;
                        uint32_t b0 = bfr[hb][nfp][s2 * 2];
                        uint32_t b1 = bfr[hb][nfp][s2 * 2 + 1];
                        mma16816(acc[0][nf], afr[ha][0], b0, b1);
                        mma16816(acc[1][nf], afr[ha][1], b0, b1);
                    }
            }
        }
        __syncthreads();
    }

    const int Nt = gridDim.x * 64;
    const bool direct = (gridDim.y == 1);
#pragma unroll
    for (int mf = 0; mf < 2; mf++)
#pragma unroll
        for (int nf = 0; nf < 4; nf++) {
            int row = wm + mf * 16 + r;
            int col = bn + wn + nf * 8 + cp;
            float* c = acc[mf][nf];
            if (direct) {
                float* p = C + (long)bz * sC + (long)row * ldc + col;
                *(float2*)p = make_float2(c[0], c[1]);
                *(float2*)(p + 8LL * ldc) = make_float2(c[2], c[3]);
            } else {
                float* p = C + ((long)(bz * gridDim.y + z) * 128 + row) * Nt + col;
                *(float2*)p = make_float2(c[0], c[1]);
                *(float2*)(p + 8LL * Nt) = make_float2(c[2], c[3]);
            }
        }
}

// ---------------------------------------------------------------------------
// Sum split-K partials
// ---------------------------------------------------------------------------
__global__ __launch_bounds__(256) void reduce_split(
    const float* __restrict__ P, float* __restrict__ C,
    int split, int Npart, int ldc)
{
    int bz = blockIdx.y;
    long idx = ((long)blockIdx.x * 256 + threadIdx.x) * 4;
    int m = (int)(idx / Npart);
    int n = (int)(idx % Npart);
    const float* base = P + (long)bz * split * TTOK * Npart + (long)m * Npart + n;
    float4 s = *(const float4*)base;
    for (int t = 1; t < split; t++) {
        float4 v = *(const float4*)(base + (long)t * TTOK * Npart);
        s.x += v.x; s.y += v.y; s.z += v.z; s.w += v.w;
    }
    *(float4*)(C + (long)m * ldc + bz * Npart + n) = s;
}

__device__ __forceinline__ float gelu_t(float x) {
    float x3 = x * x * x;
    return 0.5f * x * (1.f + tanh_f(0.7978845608028654f * (x + 0.044715f * x3)));
}

__global__ __launch_bounds__(256) void reduce_gelu_mul(
    const float* __restrict__ Pa, const float* __restrict__ Pb,
    float* __restrict__ C, int split)
{
    long idx = ((long)blockIdx.x * 256 + threadIdx.x) * 4;
    float4 a = *(const float4*)(Pa + idx);
    float4 b = *(const float4*)(Pb + idx);
    for (int t = 1; t < split; t++) {
        float4 va = *(const float4*)(Pa + idx + (long)t * TTOK * FFDIM);
        float4 vb = *(const float4*)(Pb + idx + (long)t * TTOK * FFDIM);
        a.x += va.x; a.y += va.y; a.z += va.z; a.w += va.w;
        b.x += vb.x; b.y += vb.y; b.z += vb.z; b.w += vb.w;
    }
    float4 o;
    o.x = gelu_t(a.x) * b.x; o.y = gelu_t(a.y) * b.y;
    o.z = gelu_t(a.z) * b.z; o.w = gelu_t(a.w) * b.w;
    *(float4*)(C + idx) = o;
}

// ---------------------------------------------------------------------------
// RMSNorm kernels
// ---------------------------------------------------------------------------
__global__ __launch_bounds__(256) void rms_kernel(
    const float* __restrict__ x, const float* __restrict__ w,
    float* __restrict__ y, int ncols)
{
    int row = blockIdx.x;
    const float* xr = x + (long)row * ncols;
    __shared__ float red[256];
    int tid = threadIdx.x;
    float ss = 0.f;
    for (int c = tid; c < ncols; c += 256) { float v = xr[c]; ss += v * v; }
    red[tid] = ss; __syncthreads();
    for (int s = 128; s > 0; s >>= 1) { if (tid < s) red[tid] += red[tid + s]; __syncthreads(); }
    float inv = rsqrtf(red[0] / ncols + 1e-6f);
    for (int c = tid; c < ncols; c += 256)
        y[(long)row * ncols + c] = xr[c] * inv * (1.f + w[c]);
}

__global__ __launch_bounds__(256) void add_rms_rms(
    float* __restrict__ h, const float* __restrict__ P, int split,
    const float* __restrict__ w1, const float* __restrict__ w2,
    float* __restrict__ x)
{
    int row = blockIdx.x, tid = threadIdx.x;
    __shared__ float red[256];
    float pv[5], hv[5];

    float ssp = 0.f;
#pragma unroll
    for (int j = 0; j < 5; j++) {
        int c = tid + j * 256;
        float v = 0.f;
        if (c < DMODEL) {
            const float* b = P + (long)row * DMODEL + c;
            v = b[0];
            for (int t = 1; t < split; t++) v += b[(long)t * TTOK * DMODEL];
        }
        pv[j] = v; ssp += v * v;
    }
    red[tid] = ssp; __syncthreads();
    for (int s = 128; s > 0; s >>= 1) { if (tid < s) red[tid] += red[tid + s]; __syncthreads(); }
    float inv1 = rsqrtf(red[0] / DMODEL + 1e-6f);
    __syncthreads();

    float ssh = 0.f;
#pragma unroll
    for (int j = 0; j < 5; j++) {
        int c = tid + j * 256;
        float v = 0.f;
        if (c < DMODEL) {
            v = h[(long)row * DMODEL + c] + pv[j] * inv1 * (1.f + w1[c]);
            h[(long)row * DMODEL + c] = v;
        }
        hv[j] = v; ssh += v * v;
    }
    red[tid] = ssh; __syncthreads();
    for (int s = 128; s > 0; s >>= 1) { if (tid < s) red[tid] += red[tid + s]; __syncthreads(); }
    float inv2 = rsqrtf(red[0] / DMODEL + 1e-6f);

#pragma unroll
    for (int j = 0; j < 5; j++) {
        int c = tid + j * 256;
        if (c < DMODEL)
            x[(long)row * DMODEL + c] = hv[j] * inv2 * (1.f + w2[c]);
    }
}

// ---------------------------------------------------------------------------
// kv_prep: fused rope (6-partial sum) + K copy + V transpose copy
// ---------------------------------------------------------------------------
__global__ __launch_bounds__(256) void kv_prep_kernel(
    const float* __restrict__ P,
    const float* __restrict__ qw, const float* __restrict__ kw,
    const float* __restrict__ cosp, const float* __restrict__ sinp,
    const float* __restrict__ ksrc, const float* __restrict__ vsrc,
    float* __restrict__ qout, float* __restrict__ Kfull, float* __restrict__ Vfull,
    float* __restrict__ kslice, float* __restrict__ vslice)
{
    const int bid = blockIdx.x;
    const int tid = threadIdx.x;

    if (bid < 768) {                       // rope / v-scatter: (t, section)
        const int t = bid & 127, s = bid >> 7;
        const int d = tid;
        const float* b = P + (long)t * QKVW + s * HDIM + d;
        float v = b[0];
#pragma unroll
        for (int zz = 1; zz < 6; zz++) v += b[(long)zz * TTOK * QKVW];

        if (s == 5) {                      // v
            Vfull[(long)d * STOT + CCTX + t] = v;
            vslice[(long)d * TTOK + t] = v;
            return;
        }
        __shared__ float red[256];
        __shared__ float buf[256];
        red[d] = v * v; __syncthreads();
        for (int st = 128; st > 0; st >>= 1) {
            if (d < st) red[d] += red[d + st];
            __syncthreads();
        }
        float inv = rsqrtf(red[0] / HDIM + 1e-6f);
        const float* w = (s < 4) ? qw : kw;
        float xn = v * inv * (1.f + w[d]);
        buf[d] = xn; __syncthreads();
        float rot = (d < 128) ? -buf[d + 128] : buf[d - 128];
        float r = xn * cosp[t * HDIM + d] + rot * sinp[t * HDIM + d];
        if (s < 4) {
            qout[(long)s * TTOK * HDIM + (long)t * HDIM + d] = r;
        } else {
            Kfull[(long)(CCTX + t) * HDIM + d] = r;
            kslice[(long)t * HDIM + d] = r;
        }
    } else if (bid < 768 + 1920) {         // K copy
        const int row = bid - 768;
        Kfull[(long)row * HDIM + tid] = ksrc[(long)row * HDIM + tid];
    } else {                               // V copy (transpose layout fix)
        long idx = (long)(bid - 2688) * 256 + tid;
        int d = (int)(idx / CCTX), s2 = (int)(idx % CCTX);
        Vfull[(long)d * STOT + s2] = vsrc[idx];
    }
}

// ---------------------------------------------------------------------------
// softmax with tanh soft-cap + mask
// ---------------------------------------------------------------------------
__global__ __launch_bounds__(256) void softmax_kernel(
    float* __restrict__ sc, const float* __restrict__ mask)
{
    int t = blockIdx.x, h = blockIdx.y;
    float* row = sc + ((long)h * TTOK + t) * STOT;
    const float* mrow = mask + (long)t * STOT;
    __shared__ float red[256];
    int tid = threadIdx.x;
    const float scale = 0.0625f;
    const float invcap = 1.f / 50.f;

    float vals[8];
    float vmax = -1e30f;
#pragma unroll
    for (int j = 0; j < 8; j++) {
        int s = tid + j * 256;
        float v = row[s] * scale;
        v = tanh_f(v * invcap) * 50.f + mrow[s];
        vals[j] = v;
        vmax = fmaxf(vmax, v);
    }
    red[tid] = vmax; __syncthreads();
    for (int s = 128; s > 0; s >>= 1) { if (tid < s) red[tid] = fmaxf(red[tid], red[tid + s]); __syncthreads(); }
    float m = red[0]; __syncthreads();
    float lsum = 0.f;
#pragma unroll
    for (int j = 0; j < 8; j++) { vals[j] = __expf(vals[j] - m); lsum += vals[j]; }
    red[tid] = lsum; __syncthreads();
    for (int s = 128; s > 0; s >>= 1) { if (tid < s) red[tid] += red[tid + s]; __syncthreads(); }
    float inv = 1.f / red[0];
#pragma unroll
    for (int j = 0; j < 8; j++) row[tid + j * 256] = vals[j] * inv;
}

// ---------------------------------------------------------------------------
// launch
// ---------------------------------------------------------------------------
extern "C" void kernel_launch(void* const* d_in, const int* in_sizes, int n_in,
                              void* d_out, int out_size)
{
    (void)in_sizes; (void)n_in; (void)out_size;
    const float* emb        = (const float*)d_in[0];
    const float* mask_g     = (const float*)d_in[1];
    const float* mask_l     = (const float*)d_in[2];
    const float* pe_cos     = (const float*)d_in[3];
    const float* pe_sin     = (const float*)d_in[4];
    const float* pe_cos_loc = (const float*)d_in[5];
    const float* pe_sin_loc = (const float*)d_in[6];
    const float* kv_k       = (const float*)d_in[7];
    const float* kv_v       = (const float*)d_in[8];
    const float* pre_attn_w = (const float*)d_in[9];
    const float* q_norm_w   = (const float*)d_in[10];
    const float* k_norm_w   = (const float*)d_in[11];
    const float* post_attn_w= (const float*)d_in[12];
    const float* pre_ff_w   = (const float*)d_in[13];
    const float* post_ff_w  = (const float*)d_in[14];
    const float* final_w    = (const float*)d_in[15];
    const float* w_qkv      = (const float*)d_in[16];
    const float* w_out      = (const float*)d_in[17];
    const float* w_gate     = (const float*)d_in[18];
    const float* w_up       = (const float*)d_in[19];
    const float* w_down     = (const float*)d_in[20];
    const float* w_lm       = (const float*)d_in[21];

    float* out    = (float*)d_out;
    float* logits = out;
    float* kout   = out + (long)TTOK * VOCAB;
    float* vout   = kout + (long)LAY * TTOK * HDIM;

    void* sp = nullptr;
    cudaGetSymbolAddress(&sp, g_scratch);
    float* S = (float*)sp;
    float* g_h     = S + OFF_H;
    float* g_x     = S + OFF_X;
    float* g_q     = S + OFF_Q;
    float* g_K     = S + OFF_K;
    float* g_V     = S + OFF_V;
    float* g_sc    = S + OFF_SC;
    float* g_att   = S + OFF_ATT;
    float* g_ff1   = S + OFF_FF1;
    float* g_part  = S + OFF_PART;
    float* g_partB = g_part + 2L * TTOK * FFDIM;   // "up" partial sets (2,3)

    cudaFuncSetAttribute(gemm_mma<false>,
                         cudaFuncAttributeMaxDynamicSharedMemorySize, GSM_TOTAL);
    cudaFuncSetAttribute(gemm_mma<true>,
                         cudaFuncAttributeMaxDynamicSharedMemorySize, GSM_TOTAL);

    cudaMemcpyAsync(g_h, emb, (long)TTOK * DMODEL * sizeof(float),
                    cudaMemcpyDeviceToDevice);
    rms_kernel<<<TTOK, 256>>>(g_h, pre_attn_w, g_x, DMODEL);

    for (int i = 0; i < LAY; i++) {
        bool is_local = ((i + 1) % 6 == 0);
        const float* cosP = is_local ? pe_cos_loc : pe_cos;
        const float* sinP = is_local ? pe_sin_loc : pe_sin;
        const float* mask = is_local ? mask_l : mask_g;

        // qkv = x @ w_qkv[i] : K=1152 (36 k32), split 6 -> 144 CTAs
        gemm_mma<false><<<dim3(QKVW / 64, 6, 1), 256, GSM_TOTAL>>>(
            g_x, w_qkv + (long)i * DMODEL * QKVW, g_part,
            DMODEL, DMODEL, QKVW, 0, 6, 0, 0, 0);

        // fused: rope (qkv partial-sum) + K copy + V transpose copy
        kv_prep_kernel<<<4608, 256>>>(
            g_part, q_norm_w + (long)i * HDIM, k_norm_w + (long)i * HDIM,
            cosP, sinP,
            kv_k + (long)i * CCTX * HDIM, kv_v + (long)i * HDIM * CCTX,
            g_q, g_K, g_V,
            kout + (long)i * TTOK * HDIM, vout + (long)i * HDIM * TTOK);

        // scores[h] = q[h] @ K^T : K=256 (8 k32), batch 4 -> 128 CTAs
        gemm_mma<true><<<dim3(STOT / 64, 1, NHEAD), 256, GSM_TOTAL>>>(
            g_q, g_K, g_sc,
            HDIM, HDIM, HDIM, STOT, 8,
            (long)TTOK * HDIM, 0, (long)TTOK * STOT);

        softmax_kernel<<<dim3(TTOK, NHEAD), 256>>>(g_sc, mask);

        // att[h] = attn[h] @ V^T : K=2048 (64 k32), batch 4, split 8 -> 128 CTAs
        gemm_mma<true><<<dim3(HDIM / 64, 8, NHEAD), 256, GSM_TOTAL>>>(
            g_sc, g_V, g_part,
            STOT, STOT, STOT, 0, 8,
            (long)TTOK * STOT, 0, 0);
        reduce_split<<<dim3(TTOK * HDIM / 1024, NHEAD), 256>>>(
            g_part, g_att, 8, HDIM, NHEAD * HDIM);

        // proj = att @ w_out[i] : K=1024 (32 k32), split 8 -> 144 CTAs
        gemm_mma<false><<<dim3(DMODEL / 64, 8, 1), 256, GSM_TOTAL>>>(
            g_att, w_out + (long)i * (NHEAD * HDIM) * DMODEL, g_part,
            NHEAD * HDIM, NHEAD * HDIM, DMODEL, 0, 4, 0, 0, 0);

        add_rms_rms<<<TTOK, 256>>>(
            g_h, g_part, 8,
            post_attn_w + (long)i * DMODEL, pre_ff_w + (long)i * DMODEL, g_x);

        // gate (bz=0) + up (bz=1) in ONE launch -> 432 CTAs
        gemm_mma<false><<<dim3(FFDIM / 64, 2, 2), 256, GSM_TOTAL>>>(
            g_x, w_gate + (long)i * DMODEL * FFDIM, g_part,
            DMODEL, DMODEL, FFDIM, 0, 18,
            0, (long)(w_up - w_gate), 0);
        reduce_gelu_mul<<<dim3(TTOK * FFDIM / 1024, 1), 256>>>(
            g_part, g_partB, g_ff1, 2);

        // down : K=6912 (216 k32), split 12 -> 216 CTAs
        gemm_mma<false><<<dim3(DMODEL / 64, 12, 1), 256, GSM_TOTAL>>>(
            g_ff1, w_down + (long)i * FFDIM * DMODEL, g_part,
            FFDIM, FFDIM, DMODEL, 0, 18, 0, 0, 0);

        const float* next_w = (i + 1 < LAY) ? (pre_attn_w + (long)(i + 1) * DMODEL)
                                            : final_w;
        add_rms_rms<<<TTOK, 256>>>(
            g_h, g_part, 12,
            post_ff_w + (long)i * DMODEL, next_w, g_x);
    }

    // logits = x @ w_lm : K=1152 (36 k32), 512 CTAs, no split
    gemm_mma<false><<<dim3(VOCAB / 64, 1, 1), 256, GSM_TOTAL>>>(
        g_x, w_lm, logits,
        DMODEL, DMODEL, VOCAB, VOCAB, 36, 0, 0, 0);
}